// round 4
// baseline (speedup 1.0000x reference)
#include <cuda_runtime.h>
#include <cuda_bf16.h>

#define Bb 128
#define Nn 1024
#define DMdim 64
#define K2 2048   // S * Nn

// Scratch (no allocs): static device globals
__device__ float g_gc[Bb * DMdim * Nn];                  // 32 MB
__device__ __nv_bfloat16 g_yhi[(size_t)8192 * 2048];     // 32 MB
__device__ __nv_bfloat16 g_ylo[(size_t)8192 * 2048];     // 32 MB
__device__ __nv_bfloat16 g_ahi[2 * 1024 * 1024];         // 4 MB
__device__ __nv_bfloat16 g_alo[2 * 1024 * 1024];         // 4 MB
__device__ float g_weff[128 * 68];
__device__ float g_beff[128];

// ---------------------------------------------------------------------------
__device__ __forceinline__ unsigned s2u(const void* p) {
    unsigned a;
    asm("{ .reg .u64 t; cvta.to.shared.u64 t, %1; cvt.u32.u64 %0, t; }"
        : "=r"(a) : "l"(p));
    return a;
}
#define CP16(dst, src) \
    asm volatile("cp.async.cg.shared.global [%0], [%1], 16;" :: "r"(dst), "l"(src))
#define CP_COMMIT() asm volatile("cp.async.commit_group;" ::: "memory")

// ---------------------------------------------------------------------------
// Kernel: split adj into hi/lo bf16
// ---------------------------------------------------------------------------
__global__ __launch_bounds__(256) void k_adj(const float* __restrict__ adj)
{
    int i = blockIdx.x * 256 + threadIdx.x;   // 524288 float4s
    float4 v = ((const float4*)adj)[i];
    __nv_bfloat16 h0 = __float2bfloat16(v.x);
    __nv_bfloat16 h1 = __float2bfloat16(v.y);
    __nv_bfloat16 h2 = __float2bfloat16(v.z);
    __nv_bfloat16 h3 = __float2bfloat16(v.w);
    __nv_bfloat16 l0 = __float2bfloat16(v.x - __bfloat162float(h0));
    __nv_bfloat16 l1 = __float2bfloat16(v.y - __bfloat162float(h1));
    __nv_bfloat16 l2 = __float2bfloat16(v.z - __bfloat162float(h2));
    __nv_bfloat16 l3 = __float2bfloat16(v.w - __bfloat162float(h3));
    ((__nv_bfloat162*)g_ahi)[i * 2 + 0] = __halves2bfloat162(h0, h1);
    ((__nv_bfloat162*)g_ahi)[i * 2 + 1] = __halves2bfloat162(h2, h3);
    ((__nv_bfloat162*)g_alo)[i * 2 + 0] = __halves2bfloat162(l0, l1);
    ((__nv_bfloat162*)g_alo)[i * 2 + 1] = __halves2bfloat162(l2, l3);
}

// ---------------------------------------------------------------------------
// Kernel: fold W_in into W_gc.
// W_eff[o'][c'] = sum_c W_gc[o'&63][(o'>>6)*64 + c] * W_in[c][c']   (c' < 68)
// b_eff[o']    = sum_c W_gc[o'&63][(o'>>6)*64 + c] * b_in[c]
// ---------------------------------------------------------------------------
__global__ __launch_bounds__(256) void k_weff(
    const float* __restrict__ W_in, const float* __restrict__ b_in,
    const float* __restrict__ W_gc)
{
    int tid = threadIdx.x;
    for (int i = tid; i < 128 * 68; i += 256) {
        int op = i / 68, cp = i - op * 68;
        const float* wg = W_gc + (op & 63) * 128 + (op >> 6) * 64;
        float s = 0.f;
        for (int c = 0; c < 64; c++) s = fmaf(wg[c], W_in[c * 68 + cp], s);
        g_weff[i] = s;
    }
    if (tid < 128) {
        const float* wg = W_gc + (tid & 63) * 128 + (tid >> 6) * 64;
        float s = 0.f;
        for (int c = 0; c < 64; c++) s = fmaf(wg[c], b_in[c], s);
        g_beff[tid] = s;
    }
}

// ---------------------------------------------------------------------------
// Kernel: y columns. 4 cols/thread, o-chunks of 16.
// y[(b*64+oc), s*1024+n] = b_eff[o'] + sum_{c'} W_eff[o'][c'] * in[c'][col]
// written split bf16 (hi, lo).
// ---------------------------------------------------------------------------
__global__ __launch_bounds__(256) void k_y(
    const float* __restrict__ x, const float* __restrict__ m,
    const float* __restrict__ u, const float* __restrict__ h)
{
    __shared__ float WT[68][128];   // WT[c'][o']
    __shared__ float be[128];
    for (int i = threadIdx.x; i < 128 * 68; i += 256) {
        int op = i / 68, cp = i - op * 68;
        WT[cp][op] = g_weff[i];
    }
    if (threadIdx.x < 128) be[threadIdx.x] = g_beff[threadIdx.x];
    __syncthreads();

    int b = blockIdx.x;
    int n0 = threadIdx.x * 4;

    for (int ch = 0; ch < 8; ch++) {
        int o0 = ch * 16;
        float acc[16][4];
#pragma unroll
        for (int oo = 0; oo < 16; oo++) {
            float bv = be[o0 + oo];
#pragma unroll
            for (int j = 0; j < 4; j++) acc[oo][j] = bv;
        }

#define YACC(cp, ptr) do {                                                     \
        float4 _v = *(const float4*)(ptr);                                     \
        _Pragma("unroll")                                                      \
        for (int oo = 0; oo < 16; oo++) {                                      \
            float _w = WT[cp][o0 + oo];                                        \
            acc[oo][0] = fmaf(_w, _v.x, acc[oo][0]);                           \
            acc[oo][1] = fmaf(_w, _v.y, acc[oo][1]);                           \
            acc[oo][2] = fmaf(_w, _v.z, acc[oo][2]);                           \
            acc[oo][3] = fmaf(_w, _v.w, acc[oo][3]);                           \
        }                                                                      \
    } while (0)

        YACC(0, &x[b * 1024 + n0]);
        YACC(1, &m[b * 1024 + n0]);
        YACC(2, &u[b * 2048 + n0]);
        YACC(3, &u[b * 2048 + 1024 + n0]);
        for (int c = 0; c < 64; c++)
            YACC(4 + c, &h[(b * 64 + c) * 1024 + n0]);
#undef YACC

#pragma unroll
        for (int oo = 0; oo < 16; oo++) {
            int op = o0 + oo;
            int s = op >> 6, oc = op & 63;
            size_t yi = (size_t)(b * 64 + oc) * K2 + s * 1024 + n0;
            ushort4 hiv, lov;
            __nv_bfloat16 t;
            t = __float2bfloat16(acc[oo][0]); hiv.x = *(unsigned short*)&t;
            lov.x = *(unsigned short*)&(t = __float2bfloat16(acc[oo][0] - __bfloat162float(t)));
            t = __float2bfloat16(acc[oo][1]); hiv.y = *(unsigned short*)&t;
            lov.y = *(unsigned short*)&(t = __float2bfloat16(acc[oo][1] - __bfloat162float(*(__nv_bfloat16*)&hiv.y)));
            t = __float2bfloat16(acc[oo][2]); hiv.z = *(unsigned short*)&t;
            lov.z = *(unsigned short*)&(t = __float2bfloat16(acc[oo][2] - __bfloat162float(*(__nv_bfloat16*)&hiv.z)));
            t = __float2bfloat16(acc[oo][3]); hiv.w = *(unsigned short*)&t;
            lov.w = *(unsigned short*)&(t = __float2bfloat16(acc[oo][3] - __bfloat162float(*(__nv_bfloat16*)&hiv.w)));
            *(ushort4*)&g_yhi[yi] = hiv;
            *(ushort4*)&g_ylo[yi] = lov;
        }
    }
}

// ---------------------------------------------------------------------------
// GEMM: gc[m, w] = b_gc[m&63] + 3-pass split-bf16 mma.sync
// BM=128 BN=256 BK=32, 8 warps (2x4), warp tile 64x64, 3-stage cp.async.
// ---------------------------------------------------------------------------
#define BM 128
#define BN 256
#define BK 32
#define RS 40                       // smem row stride (bf16)
#define ASTG (128 * RS * 2)         // 10240 B
#define BSTG (256 * RS * 2)         // 20480 B
#define STGB (ASTG + BSTG)          // 30720 B per stage
#define GDYN (3 * STGB)

__device__ __forceinline__ void ldsm4(unsigned* r, unsigned addr) {
    asm volatile("ldmatrix.sync.aligned.m8n8.x4.shared.b16 {%0,%1,%2,%3}, [%4];"
                 : "=r"(r[0]), "=r"(r[1]), "=r"(r[2]), "=r"(r[3]) : "r"(addr));
}
__device__ __forceinline__ void mma16816(float* c, const unsigned* a,
                                         unsigned b0, unsigned b1) {
    asm volatile(
        "mma.sync.aligned.m16n8k16.row.col.f32.bf16.bf16.f32 "
        "{%0,%1,%2,%3}, {%4,%5,%6,%7}, {%8,%9}, {%0,%1,%2,%3};"
        : "+f"(c[0]), "+f"(c[1]), "+f"(c[2]), "+f"(c[3])
        : "r"(a[0]), "r"(a[1]), "r"(a[2]), "r"(a[3]), "r"(b0), "r"(b1));
}

__device__ __forceinline__ void load_chunk(unsigned base, int st, int t,
                                           int bm, int bn, int tid)
{
    int p = t >> 6;                  // pass 0..2
    int k0 = (t & 63) * BK;
    int s = k0 >> 10;
    int v0 = k0 & 1023;
    const __nv_bfloat16* Ap = (p == 1) ? g_ylo : g_yhi;
    const __nv_bfloat16* Bp = (p == 2) ? g_alo : g_ahi;
    unsigned ab = base + st * STGB;
    unsigned bb = ab + ASTG;
#pragma unroll
    for (int i = 0; i < 2; i++) {               // A: 512 units
        int u2 = tid + i * 256;
        int row = u2 >> 2, j = u2 & 3;
        CP16(ab + (row * RS + j * 8) * 2,
             (const char*)(Ap + (size_t)(bm + row) * K2 + k0 + j * 8));
    }
#pragma unroll
    for (int i = 0; i < 4; i++) {               // B: 1024 units
        int u2 = tid + i * 256;
        int row = u2 >> 2, j = u2 & 3;
        CP16(bb + (row * RS + j * 8) * 2,
             (const char*)(Bp + (size_t)s * 1048576 +
                           (size_t)(bn + row) * 1024 + v0 + j * 8));
    }
    CP_COMMIT();
}

__global__ __launch_bounds__(256, 1) void k_gemm_mma(const float* __restrict__ b_gc)
{
    extern __shared__ __align__(16) char dsm[];
    unsigned base = s2u(dsm);

    int tid = threadIdx.x;
    int lane = tid & 31;
    int wid = tid >> 5;
    int wm = wid >> 2;        // 0..1  (64-row group)
    int wn = wid & 3;         // 0..3  (64-col group)
    int bm = blockIdx.y * BM;
    int bn = blockIdx.x * BN;

    float acc[4][4][2][4];
#pragma unroll
    for (int a = 0; a < 4; a++)
#pragma unroll
        for (int b = 0; b < 4; b++)
#pragma unroll
            for (int c = 0; c < 2; c++)
#pragma unroll
                for (int d = 0; d < 4; d++) acc[a][b][c][d] = 0.f;

    load_chunk(base, 0, 0, bm, bn, tid);
    load_chunk(base, 1, 1, bm, bn, tid);

    int st = 0;
    for (int t = 0; t < 192; t++) {
        if (t == 191) asm volatile("cp.async.wait_group 0;" ::: "memory");
        else          asm volatile("cp.async.wait_group 1;" ::: "memory");
        __syncthreads();

        if (t + 2 < 192) {
            int st2 = st + 2; if (st2 >= 3) st2 -= 3;
            load_chunk(base, st2, t + 2, bm, bn, tid);
        }

        unsigned abuf = base + st * STGB;
        unsigned bbuf = abuf + ASTG;

#pragma unroll
        for (int kk = 0; kk < 2; kk++) {
            int kb = kk * 16;
            unsigned ar[4][4];
#pragma unroll
            for (int mf = 0; mf < 4; mf++) {
                int mrow = wm * 64 + mf * 16 + (lane & 7) + ((lane >> 3) & 1) * 8;
                int kcol = kb + (lane >> 4) * 8;
                ldsm4(ar[mf], abuf + (mrow * RS + kcol) * 2);
            }
            unsigned br[4][4];
#pragma unroll
            for (int nt = 0; nt < 4; nt++) {
                int nrow = wn * 64 + nt * 16 + (lane & 7) + (lane >> 4) * 8;
                int kcol = kb + ((lane >> 3) & 1) * 8;
                ldsm4(br[nt], bbuf + (nrow * RS + kcol) * 2);
            }
#pragma unroll
            for (int mf = 0; mf < 4; mf++)
#pragma unroll
                for (int nt = 0; nt < 4; nt++) {
                    mma16816(acc[mf][nt][0], ar[mf], br[nt][0], br[nt][1]);
                    mma16816(acc[mf][nt][1], ar[mf], br[nt][2], br[nt][3]);
                }
        }
        st++; if (st >= 3) st = 0;
    }

    // epilogue
#pragma unroll
    for (int mf = 0; mf < 4; mf++) {
        int r0 = bm + wm * 64 + mf * 16 + (lane >> 2);
        float bv0 = __ldg(&b_gc[r0 & 63]);
        float bv1 = __ldg(&b_gc[(r0 + 8) & 63]);
#pragma unroll
        for (int nt = 0; nt < 4; nt++)
#pragma unroll
            for (int h8 = 0; h8 < 2; h8++) {
                int col = bn + wn * 64 + nt * 16 + h8 * 8 + (lane & 3) * 2;
                float* c4 = acc[mf][nt][h8];
                *(float2*)&g_gc[(size_t)r0 * 1024 + col] =
                    make_float2(c4[0] + bv0, c4[1] + bv0);
                *(float2*)&g_gc[(size_t)(r0 + 8) * 1024 + col] =
                    make_float2(c4[2] + bv1, c4[3] + bv1);
            }
    }
}

// ---------------------------------------------------------------------------
// k_out: 4 cols/thread, o-chunks of 16, transposed W_out in smem.
// ---------------------------------------------------------------------------
__global__ __launch_bounds__(256) void k_out(
    const float* __restrict__ h, const float* __restrict__ W_out,
    const float* __restrict__ b_out, const float* __restrict__ W_read,
    const float* __restrict__ b_read, const float* __restrict__ prelu_w,
    float* __restrict__ out)
{
    __shared__ float WoT[128][64];   // WoT[c][o]
    __shared__ float Wr[128];
    __shared__ float bo[64];
    for (int i = threadIdx.x; i < 64 * 128; i += 256) {
        int o = i >> 7, c = i & 127;
        WoT[c][o] = W_out[i];
    }
    if (threadIdx.x < 128) Wr[threadIdx.x] = W_read[threadIdx.x];
    if (threadIdx.x < 64) bo[threadIdx.x] = b_out[threadIdx.x];
    __syncthreads();

    int b = blockIdx.x;
    int n0 = threadIdx.x * 4;
    float pw = __ldg(prelu_w);
    float br = __ldg(b_read);
    float racc[4] = {br, br, br, br};
    float* out2 = out + (size_t)Bb * Nn;

    for (int ch = 0; ch < 4; ch++) {
        int o0 = ch * 16;
        float acc[16][4];
#pragma unroll
        for (int oo = 0; oo < 16; oo++) {
            float bv = bo[o0 + oo];
#pragma unroll
            for (int j = 0; j < 4; j++) acc[oo][j] = bv;
        }
        for (int c = 0; c < 64; c++) {
            float4 g = *(const float4*)&g_gc[(size_t)(b * 64 + c) * 1024 + n0];
#pragma unroll
            for (int oo = 0; oo < 16; oo++) {
                float w = WoT[c][o0 + oo];
                acc[oo][0] = fmaf(w, g.x, acc[oo][0]);
                acc[oo][1] = fmaf(w, g.y, acc[oo][1]);
                acc[oo][2] = fmaf(w, g.z, acc[oo][2]);
                acc[oo][3] = fmaf(w, g.w, acc[oo][3]);
            }
        }
        for (int c = 0; c < 64; c++) {
            float4 hv = *(const float4*)&h[(size_t)(b * 64 + c) * 1024 + n0];
#pragma unroll
            for (int oo = 0; oo < 16; oo++) {
                float w = WoT[64 + c][o0 + oo];
                acc[oo][0] = fmaf(w, hv.x, acc[oo][0]);
                acc[oo][1] = fmaf(w, hv.y, acc[oo][1]);
                acc[oo][2] = fmaf(w, hv.z, acc[oo][2]);
                acc[oo][3] = fmaf(w, hv.w, acc[oo][3]);
            }
        }
#pragma unroll
        for (int oo = 0; oo < 16; oo++) {
            int o = o0 + oo;
            float wr = Wr[o];
            float4 p;
            p.x = acc[oo][0] >= 0.f ? acc[oo][0] : pw * acc[oo][0];
            p.y = acc[oo][1] >= 0.f ? acc[oo][1] : pw * acc[oo][1];
            p.z = acc[oo][2] >= 0.f ? acc[oo][2] : pw * acc[oo][2];
            p.w = acc[oo][3] >= 0.f ? acc[oo][3] : pw * acc[oo][3];
            *(float4*)&out2[(size_t)(b * 128 + o) * 1024 + n0] = p;
            racc[0] = fmaf(wr, p.x, racc[0]);
            racc[1] = fmaf(wr, p.y, racc[1]);
            racc[2] = fmaf(wr, p.z, racc[2]);
            racc[3] = fmaf(wr, p.w, racc[3]);
        }
    }

    for (int c = 0; c < 64; c++) {
        float4 hv = *(const float4*)&h[(size_t)(b * 64 + c) * 1024 + n0];
        *(float4*)&out2[(size_t)(b * 128 + 64 + c) * 1024 + n0] = hv;
        float wr = Wr[64 + c];
        racc[0] = fmaf(wr, hv.x, racc[0]);
        racc[1] = fmaf(wr, hv.y, racc[1]);
        racc[2] = fmaf(wr, hv.z, racc[2]);
        racc[3] = fmaf(wr, hv.w, racc[3]);
    }
    *(float4*)&out[(size_t)b * 1024 + n0] =
        make_float4(racc[0], racc[1], racc[2], racc[3]);
}

// ---------------------------------------------------------------------------
extern "C" void kernel_launch(void* const* d_in, const int* in_sizes, int n_in,
                              void* d_out, int out_size)
{
    const float* x      = (const float*)d_in[0];
    const float* m      = (const float*)d_in[1];
    const float* u      = (const float*)d_in[2];
    const float* h      = (const float*)d_in[3];
    const float* adj    = (const float*)d_in[4];
    const float* W_in   = (const float*)d_in[5];
    const float* b_in   = (const float*)d_in[6];
    const float* W_gc   = (const float*)d_in[7];
    const float* b_gc   = (const float*)d_in[8];
    const float* W_out  = (const float*)d_in[9];
    const float* b_out  = (const float*)d_in[10];
    const float* W_read = (const float*)d_in[11];
    const float* b_read = (const float*)d_in[12];
    const float* prelu  = (const float*)d_in[13];
    float* out = (float*)d_out;

    cudaFuncSetAttribute(k_gemm_mma, cudaFuncAttributeMaxDynamicSharedMemorySize, GDYN);

    k_adj<<<2048, 256>>>(adj);
    k_weff<<<1, 256>>>(W_in, b_in, W_gc);
    k_y<<<Bb, 256>>>(x, m, u, h);
    dim3 g(Nn / BN, (Bb * DMdim) / BM);   // (4, 64) = 256 CTAs
    k_gemm_mma<<<g, 256, GDYN>>>(b_gc);
    k_out<<<Bb, 256>>>(h, W_out, b_out, W_read, b_read, prelu, out);
}

// round 5
// speedup vs baseline: 1.2318x; 1.2318x over previous
#include <cuda_runtime.h>
#include <cuda_bf16.h>

#define Bb 128
#define Nn 1024
#define DMdim 64
#define K2 2048   // S * Nn

// Scratch (no allocs): static device globals
__device__ float g_gc[Bb * DMdim * Nn];                  // 32 MB
__device__ __nv_bfloat16 g_yhi[(size_t)8192 * 2048];     // 32 MB
__device__ __nv_bfloat16 g_ylo[(size_t)8192 * 2048];     // 32 MB
__device__ __nv_bfloat16 g_ahi[2 * 1024 * 1024];         // 4 MB
__device__ __nv_bfloat16 g_alo[2 * 1024 * 1024];         // 4 MB
__device__ float g_weff[128 * 68];
__device__ float g_beff[128];

// ---------------------------------------------------------------------------
__device__ __forceinline__ unsigned s2u(const void* p) {
    unsigned a;
    asm("{ .reg .u64 t; cvta.to.shared.u64 t, %1; cvt.u32.u64 %0, t; }"
        : "=r"(a) : "l"(p));
    return a;
}
#define CP16(dst, src) \
    asm volatile("cp.async.cg.shared.global [%0], [%1], 16;" :: "r"(dst), "l"(src))
#define CP_COMMIT() asm volatile("cp.async.commit_group;" ::: "memory")

// ---------------------------------------------------------------------------
// split adj into hi/lo bf16
// ---------------------------------------------------------------------------
__global__ __launch_bounds__(256) void k_adj(const float* __restrict__ adj)
{
    int i = blockIdx.x * 256 + threadIdx.x;   // 524288 float4s
    float4 v = ((const float4*)adj)[i];
    __nv_bfloat16 h0 = __float2bfloat16(v.x);
    __nv_bfloat16 h1 = __float2bfloat16(v.y);
    __nv_bfloat16 h2 = __float2bfloat16(v.z);
    __nv_bfloat16 h3 = __float2bfloat16(v.w);
    __nv_bfloat16 l0 = __float2bfloat16(v.x - __bfloat162float(h0));
    __nv_bfloat16 l1 = __float2bfloat16(v.y - __bfloat162float(h1));
    __nv_bfloat16 l2 = __float2bfloat16(v.z - __bfloat162float(h2));
    __nv_bfloat16 l3 = __float2bfloat16(v.w - __bfloat162float(h3));
    ((__nv_bfloat162*)g_ahi)[i * 2 + 0] = __halves2bfloat162(h0, h1);
    ((__nv_bfloat162*)g_ahi)[i * 2 + 1] = __halves2bfloat162(h2, h3);
    ((__nv_bfloat162*)g_alo)[i * 2 + 0] = __halves2bfloat162(l0, l1);
    ((__nv_bfloat162*)g_alo)[i * 2 + 1] = __halves2bfloat162(l2, l3);
}

// ---------------------------------------------------------------------------
// fold W_in into W_gc:  W_eff[o'][c'] (o' in [0,128), c' in [0,68))
// ---------------------------------------------------------------------------
__global__ __launch_bounds__(256) void k_weff(
    const float* __restrict__ W_in, const float* __restrict__ b_in,
    const float* __restrict__ W_gc)
{
    int tid = threadIdx.x;
    for (int i = tid; i < 128 * 68; i += 256) {
        int op = i / 68, cp = i - op * 68;
        const float* wg = W_gc + (op & 63) * 128 + (op >> 6) * 64;
        float s = 0.f;
        for (int c = 0; c < 64; c++) s = fmaf(wg[c], W_in[c * 68 + cp], s);
        g_weff[i] = s;
    }
    if (tid < 128) {
        const float* wg = W_gc + (tid & 63) * 128 + (tid >> 6) * 64;
        float s = 0.f;
        for (int c = 0; c < 64; c++) s = fmaf(wg[c], b_in[c], s);
        g_beff[tid] = s;
    }
}

// ---------------------------------------------------------------------------
// k_y: 2 cols/thread, o-chunks of 16, grid = 256 blocks.
// y[(b*64+oc), s*1024+n] = b_eff[o'] + sum_{c'} W_eff[o'][c'] * in[c'][n]
// stored as split bf16 (hi, lo).
// ---------------------------------------------------------------------------
__global__ __launch_bounds__(256) void k_y(
    const float* __restrict__ x, const float* __restrict__ m,
    const float* __restrict__ u, const float* __restrict__ h)
{
    __shared__ float WT[68][128];   // WT[c'][o']
    __shared__ float be[128];
    for (int i = threadIdx.x; i < 128 * 68; i += 256) {
        int op = i / 68, cp = i - op * 68;
        WT[cp][op] = g_weff[i];
    }
    if (threadIdx.x < 128) be[threadIdx.x] = g_beff[threadIdx.x];
    __syncthreads();

    int b = blockIdx.x >> 1;
    int n0 = (blockIdx.x & 1) * 512 + threadIdx.x * 2;

    for (int ch = 0; ch < 8; ch++) {
        int o0 = ch * 16;
        float acc[16][2];
#pragma unroll
        for (int oo = 0; oo < 16; oo++) {
            float bv = be[o0 + oo];
            acc[oo][0] = bv; acc[oo][1] = bv;
        }

#define YACC(cp, ptr) do {                                                     \
        float2 _v = *(const float2*)(ptr);                                     \
        _Pragma("unroll")                                                      \
        for (int oo = 0; oo < 16; oo++) {                                      \
            float _w = WT[cp][o0 + oo];                                        \
            acc[oo][0] = fmaf(_w, _v.x, acc[oo][0]);                           \
            acc[oo][1] = fmaf(_w, _v.y, acc[oo][1]);                           \
        }                                                                      \
    } while (0)

        YACC(0, &x[b * 1024 + n0]);
        YACC(1, &m[b * 1024 + n0]);
        YACC(2, &u[b * 2048 + n0]);
        YACC(3, &u[b * 2048 + 1024 + n0]);
        for (int c = 0; c < 64; c++)
            YACC(4 + c, &h[(b * 64 + c) * 1024 + n0]);
#undef YACC

#pragma unroll
        for (int oo = 0; oo < 16; oo++) {
            int op = o0 + oo;
            int s = op >> 6, oc = op & 63;
            size_t yi = (size_t)(b * 64 + oc) * K2 + s * 1024 + n0;
            __nv_bfloat16 h0 = __float2bfloat16(acc[oo][0]);
            __nv_bfloat16 h1 = __float2bfloat16(acc[oo][1]);
            __nv_bfloat16 l0 = __float2bfloat16(acc[oo][0] - __bfloat162float(h0));
            __nv_bfloat16 l1 = __float2bfloat16(acc[oo][1] - __bfloat162float(h1));
            *(__nv_bfloat162*)&g_yhi[yi] = __halves2bfloat162(h0, h1);
            *(__nv_bfloat162*)&g_ylo[yi] = __halves2bfloat162(l0, l1);
        }
    }
}

// ---------------------------------------------------------------------------
// GEMM: gc[m, w] = b_gc[m&63] + 3-pass split-bf16 mma.sync
// BM=128 BN=128 BK=32, 8 warps (4x2), warp tile 32x64, 3-stage cp.async,
// one __syncthreads per chunk, __launch_bounds__(256,2) -> 2 CTAs/SM.
// ---------------------------------------------------------------------------
#define BM 128
#define BN 128
#define BK 32
#define RS 40                       // smem row stride (bf16)
#define ASTG (128 * RS * 2)         // 10240 B
#define STGB (2 * ASTG)             // 20480 B per stage (A + B)
#define GDYN (3 * STGB)             // 61440 B

__device__ __forceinline__ void ldsm4(unsigned* r, unsigned addr) {
    asm volatile("ldmatrix.sync.aligned.m8n8.x4.shared.b16 {%0,%1,%2,%3}, [%4];"
                 : "=r"(r[0]), "=r"(r[1]), "=r"(r[2]), "=r"(r[3]) : "r"(addr));
}
__device__ __forceinline__ void mma16816(float* c, const unsigned* a,
                                         unsigned b0, unsigned b1) {
    asm volatile(
        "mma.sync.aligned.m16n8k16.row.col.f32.bf16.bf16.f32 "
        "{%0,%1,%2,%3}, {%4,%5,%6,%7}, {%8,%9}, {%0,%1,%2,%3};"
        : "+f"(c[0]), "+f"(c[1]), "+f"(c[2]), "+f"(c[3])
        : "r"(a[0]), "r"(a[1]), "r"(a[2]), "r"(a[3]), "r"(b0), "r"(b1));
}

__device__ __forceinline__ void load_chunk(unsigned base, int st, int t,
                                           int bm, int bn, int tid)
{
    int p = t >> 6;                  // pass 0..2
    int k0 = (t & 63) * BK;
    int s = k0 >> 10;
    int v0 = k0 & 1023;
    const __nv_bfloat16* Ap = (p == 1) ? g_ylo : g_yhi;
    const __nv_bfloat16* Bp = (p == 2) ? g_alo : g_ahi;
    unsigned ab = base + st * STGB;
    unsigned bb = ab + ASTG;
#pragma unroll
    for (int i = 0; i < 2; i++) {               // A: 512 16B units
        int u2 = tid + i * 256;
        int row = u2 >> 2, j = u2 & 3;
        CP16(ab + (row * RS + j * 8) * 2,
             (const char*)(Ap + (size_t)(bm + row) * K2 + k0 + j * 8));
    }
#pragma unroll
    for (int i = 0; i < 2; i++) {               // B: 512 16B units
        int u2 = tid + i * 256;
        int row = u2 >> 2, j = u2 & 3;
        CP16(bb + (row * RS + j * 8) * 2,
             (const char*)(Bp + (size_t)s * 1048576 +
                           (size_t)(bn + row) * 1024 + v0 + j * 8));
    }
    CP_COMMIT();
}

__global__ __launch_bounds__(256, 2) void k_gemm_mma(const float* __restrict__ b_gc)
{
    extern __shared__ __align__(16) char dsm[];
    unsigned base = s2u(dsm);

    int tid = threadIdx.x;
    int lane = tid & 31;
    int wid = tid >> 5;
    int wm = wid >> 1;        // 0..3 (32-row group)
    int wn = wid & 1;         // 0..1 (64-col group)
    int bm = blockIdx.y * BM;
    int bn = blockIdx.x * BN;

    float acc[2][8][4];
#pragma unroll
    for (int i = 0; i < 2; i++)
#pragma unroll
        for (int j = 0; j < 8; j++)
#pragma unroll
            for (int q = 0; q < 4; q++) acc[i][j][q] = 0.f;

    load_chunk(base, 0, 0, bm, bn, tid);
    load_chunk(base, 1, 1, bm, bn, tid);

    int st = 0;
    for (int t = 0; t < 192; t++) {
        if (t == 191) asm volatile("cp.async.wait_group 0;" ::: "memory");
        else          asm volatile("cp.async.wait_group 1;" ::: "memory");
        __syncthreads();

        if (t + 2 < 192) {
            int st2 = st + 2; if (st2 >= 3) st2 -= 3;
            load_chunk(base, st2, t + 2, bm, bn, tid);
        }

        unsigned abuf = base + st * STGB;
        unsigned bbuf = abuf + ASTG;

#pragma unroll
        for (int kk = 0; kk < 2; kk++) {
            int kb = kk * 16;
            unsigned ar[2][4];
#pragma unroll
            for (int mf = 0; mf < 2; mf++) {
                int mrow = wm * 32 + mf * 16 + (lane & 7) + ((lane >> 3) & 1) * 8;
                int kcol = kb + (lane >> 4) * 8;
                ldsm4(ar[mf], abuf + (mrow * RS + kcol) * 2);
            }
            unsigned br[4][4];
#pragma unroll
            for (int nt = 0; nt < 4; nt++) {
                int nrow = wn * 64 + nt * 16 + (lane & 7) + (lane >> 4) * 8;
                int kcol = kb + ((lane >> 3) & 1) * 8;
                ldsm4(br[nt], bbuf + (nrow * RS + kcol) * 2);
            }
#pragma unroll
            for (int mf = 0; mf < 2; mf++)
#pragma unroll
                for (int nt = 0; nt < 4; nt++) {
                    mma16816(acc[mf][nt * 2 + 0], ar[mf], br[nt][0], br[nt][1]);
                    mma16816(acc[mf][nt * 2 + 1], ar[mf], br[nt][2], br[nt][3]);
                }
        }
        st++; if (st >= 3) st = 0;
    }

    // epilogue: add bias, store fp32 to g_gc
#pragma unroll
    for (int mf = 0; mf < 2; mf++) {
        int r0 = bm + wm * 32 + mf * 16 + (lane >> 2);
        float bv0 = __ldg(&b_gc[r0 & 63]);
        float bv1 = __ldg(&b_gc[(r0 + 8) & 63]);
#pragma unroll
        for (int nf = 0; nf < 8; nf++) {
            int col = bn + wn * 64 + nf * 8 + (lane & 3) * 2;
            float* c4 = acc[mf][nf];
            *(float2*)&g_gc[(size_t)r0 * 1024 + col] =
                make_float2(c4[0] + bv0, c4[1] + bv0);
            *(float2*)&g_gc[(size_t)(r0 + 8) * 1024 + col] =
                make_float2(c4[2] + bv1, c4[3] + bv1);
        }
    }
}

// ---------------------------------------------------------------------------
// k_out: 2 cols/thread, o-chunks of 16, grid = 256 blocks.
// ---------------------------------------------------------------------------
__global__ __launch_bounds__(256) void k_out(
    const float* __restrict__ h, const float* __restrict__ W_out,
    const float* __restrict__ b_out, const float* __restrict__ W_read,
    const float* __restrict__ b_read, const float* __restrict__ prelu_w,
    float* __restrict__ out)
{
    __shared__ float WoT[128][64];   // WoT[c][o]
    __shared__ float Wr[128];
    __shared__ float bo[64];
    for (int i = threadIdx.x; i < 64 * 128; i += 256) {
        int o = i >> 7, c = i & 127;
        WoT[c][o] = W_out[i];
    }
    if (threadIdx.x < 128) Wr[threadIdx.x] = W_read[threadIdx.x];
    if (threadIdx.x < 64) bo[threadIdx.x] = b_out[threadIdx.x];
    __syncthreads();

    int b = blockIdx.x >> 1;
    int n0 = (blockIdx.x & 1) * 512 + threadIdx.x * 2;
    float pw = __ldg(prelu_w);
    float brd = __ldg(b_read);
    float racc[2] = {brd, brd};
    float* out2 = out + (size_t)Bb * Nn;

    for (int ch = 0; ch < 4; ch++) {
        int o0 = ch * 16;
        float acc[16][2];
#pragma unroll
        for (int oo = 0; oo < 16; oo++) {
            float bv = bo[o0 + oo];
            acc[oo][0] = bv; acc[oo][1] = bv;
        }
        for (int c = 0; c < 64; c++) {
            float2 g = *(const float2*)&g_gc[(size_t)(b * 64 + c) * 1024 + n0];
#pragma unroll
            for (int oo = 0; oo < 16; oo++) {
                float w = WoT[c][o0 + oo];
                acc[oo][0] = fmaf(w, g.x, acc[oo][0]);
                acc[oo][1] = fmaf(w, g.y, acc[oo][1]);
            }
        }
        for (int c = 0; c < 64; c++) {
            float2 hv = *(const float2*)&h[(size_t)(b * 64 + c) * 1024 + n0];
#pragma unroll
            for (int oo = 0; oo < 16; oo++) {
                float w = WoT[64 + c][o0 + oo];
                acc[oo][0] = fmaf(w, hv.x, acc[oo][0]);
                acc[oo][1] = fmaf(w, hv.y, acc[oo][1]);
            }
        }
#pragma unroll
        for (int oo = 0; oo < 16; oo++) {
            int o = o0 + oo;
            float wr = Wr[o];
            float2 p;
            p.x = acc[oo][0] >= 0.f ? acc[oo][0] : pw * acc[oo][0];
            p.y = acc[oo][1] >= 0.f ? acc[oo][1] : pw * acc[oo][1];
            *(float2*)&out2[(size_t)(b * 128 + o) * 1024 + n0] = p;
            racc[0] = fmaf(wr, p.x, racc[0]);
            racc[1] = fmaf(wr, p.y, racc[1]);
        }
    }

    for (int c = 0; c < 64; c++) {
        float2 hv = *(const float2*)&h[(size_t)(b * 64 + c) * 1024 + n0];
        *(float2*)&out2[(size_t)(b * 128 + 64 + c) * 1024 + n0] = hv;
        float wr = Wr[64 + c];
        racc[0] = fmaf(wr, hv.x, racc[0]);
        racc[1] = fmaf(wr, hv.y, racc[1]);
    }
    *(float2*)&out[(size_t)b * 1024 + n0] = make_float2(racc[0], racc[1]);
}

// ---------------------------------------------------------------------------
extern "C" void kernel_launch(void* const* d_in, const int* in_sizes, int n_in,
                              void* d_out, int out_size)
{
    const float* x      = (const float*)d_in[0];
    const float* m      = (const float*)d_in[1];
    const float* u      = (const float*)d_in[2];
    const float* h      = (const float*)d_in[3];
    const float* adj    = (const float*)d_in[4];
    const float* W_in   = (const float*)d_in[5];
    const float* b_in   = (const float*)d_in[6];
    const float* W_gc   = (const float*)d_in[7];
    const float* b_gc   = (const float*)d_in[8];
    const float* W_out  = (const float*)d_in[9];
    const float* b_out  = (const float*)d_in[10];
    const float* W_read = (const float*)d_in[11];
    const float* b_read = (const float*)d_in[12];
    const float* prelu  = (const float*)d_in[13];
    float* out = (float*)d_out;

    cudaFuncSetAttribute(k_gemm_mma, cudaFuncAttributeMaxDynamicSharedMemorySize, GDYN);

    k_adj<<<2048, 256>>>(adj);
    k_weff<<<1, 256>>>(W_in, b_in, W_gc);
    k_y<<<256, 256>>>(x, m, u, h);
    dim3 g(Nn / BN, (Bb * DMdim) / BM);   // (8, 64) = 512 CTAs
    k_gemm_mma<<<g, 256, GDYN>>>(b_gc);
    k_out<<<256, 256>>>(h, W_out, b_out, W_read, b_read, prelu, out);
}

// round 6
// speedup vs baseline: 1.4268x; 1.1583x over previous
#include <cuda_runtime.h>
#include <cuda_bf16.h>

#define Bb 128
#define Nn 1024
#define DMdim 64
#define K2 2048   // S * Nn

// Scratch (no allocs): static device globals
__device__ float g_gc[Bb * DMdim * Nn];                  // 32 MB
__device__ __nv_bfloat16 g_yhi[(size_t)8192 * 2048];     // 32 MB
__device__ __nv_bfloat16 g_ylo[(size_t)8192 * 2048];     // 32 MB
__device__ __nv_bfloat16 g_ahi[2 * 1024 * 1024];         // 4 MB
__device__ __nv_bfloat16 g_alo[2 * 1024 * 1024];         // 4 MB
__device__ float g_weff[128 * 68];
__device__ float g_beff[128];

// ---------------------------------------------------------------------------
__device__ __forceinline__ unsigned s2u(const void* p) {
    unsigned a;
    asm("{ .reg .u64 t; cvta.to.shared.u64 t, %1; cvt.u32.u64 %0, t; }"
        : "=r"(a) : "l"(p));
    return a;
}
#define CP16(dst, src) \
    asm volatile("cp.async.cg.shared.global [%0], [%1], 16;" :: "r"(dst), "l"(src))
#define CP_COMMIT() asm volatile("cp.async.commit_group;" ::: "memory")

// ---------------------------------------------------------------------------
// split adj into hi/lo bf16
// ---------------------------------------------------------------------------
__global__ __launch_bounds__(256) void k_adj(const float* __restrict__ adj)
{
    int i = blockIdx.x * 256 + threadIdx.x;   // 524288 float4s
    float4 v = ((const float4*)adj)[i];
    __nv_bfloat16 h0 = __float2bfloat16(v.x);
    __nv_bfloat16 h1 = __float2bfloat16(v.y);
    __nv_bfloat16 h2 = __float2bfloat16(v.z);
    __nv_bfloat16 h3 = __float2bfloat16(v.w);
    __nv_bfloat16 l0 = __float2bfloat16(v.x - __bfloat162float(h0));
    __nv_bfloat16 l1 = __float2bfloat16(v.y - __bfloat162float(h1));
    __nv_bfloat16 l2 = __float2bfloat16(v.z - __bfloat162float(h2));
    __nv_bfloat16 l3 = __float2bfloat16(v.w - __bfloat162float(h3));
    ((__nv_bfloat162*)g_ahi)[i * 2 + 0] = __halves2bfloat162(h0, h1);
    ((__nv_bfloat162*)g_ahi)[i * 2 + 1] = __halves2bfloat162(h2, h3);
    ((__nv_bfloat162*)g_alo)[i * 2 + 0] = __halves2bfloat162(l0, l1);
    ((__nv_bfloat162*)g_alo)[i * 2 + 1] = __halves2bfloat162(l2, l3);
}

// ---------------------------------------------------------------------------
// fold W_in into W_gc:  W_eff[o'][c'] (o' in [0,128), c' in [0,68))
// ---------------------------------------------------------------------------
__global__ __launch_bounds__(256) void k_weff(
    const float* __restrict__ W_in, const float* __restrict__ b_in,
    const float* __restrict__ W_gc)
{
    int tid = threadIdx.x;
    for (int i = tid; i < 128 * 68; i += 256) {
        int op = i / 68, cp = i - op * 68;
        const float* wg = W_gc + (op & 63) * 128 + (op >> 6) * 64;
        float s = 0.f;
        for (int c = 0; c < 64; c++) s = fmaf(wg[c], W_in[c * 68 + cp], s);
        g_weff[i] = s;
    }
    if (tid < 128) {
        const float* wg = W_gc + (tid & 63) * 128 + (tid >> 6) * 64;
        float s = 0.f;
        for (int c = 0; c < 64; c++) s = fmaf(wg[c], b_in[c], s);
        g_beff[tid] = s;
    }
}

// ---------------------------------------------------------------------------
// k_y: 128 thr/block, 512 blocks, 2 cols/thread, o-chunks of 16.
// ---------------------------------------------------------------------------
__global__ __launch_bounds__(128) void k_y(
    const float* __restrict__ x, const float* __restrict__ m,
    const float* __restrict__ u, const float* __restrict__ h)
{
    __shared__ float WT[68][128];   // WT[c'][o']
    __shared__ float be[128];
    for (int i = threadIdx.x; i < 128 * 68; i += 128) {
        int op = i / 68, cp = i - op * 68;
        WT[cp][op] = g_weff[i];
    }
    be[threadIdx.x] = g_beff[threadIdx.x];
    __syncthreads();

    int b = blockIdx.x >> 2;
    int n0 = (blockIdx.x & 3) * 256 + threadIdx.x * 2;

    for (int ch = 0; ch < 8; ch++) {
        int o0 = ch * 16;
        float acc[16][2];
#pragma unroll
        for (int oo = 0; oo < 16; oo++) {
            float bv = be[o0 + oo];
            acc[oo][0] = bv; acc[oo][1] = bv;
        }

#define YACC(cp, ptr) do {                                                     \
        float2 _v = *(const float2*)(ptr);                                     \
        _Pragma("unroll")                                                      \
        for (int oo = 0; oo < 16; oo++) {                                      \
            float _w = WT[cp][o0 + oo];                                        \
            acc[oo][0] = fmaf(_w, _v.x, acc[oo][0]);                           \
            acc[oo][1] = fmaf(_w, _v.y, acc[oo][1]);                           \
        }                                                                      \
    } while (0)

        YACC(0, &x[b * 1024 + n0]);
        YACC(1, &m[b * 1024 + n0]);
        YACC(2, &u[b * 2048 + n0]);
        YACC(3, &u[b * 2048 + 1024 + n0]);
        for (int c = 0; c < 64; c++)
            YACC(4 + c, &h[(b * 64 + c) * 1024 + n0]);
#undef YACC

#pragma unroll
        for (int oo = 0; oo < 16; oo++) {
            int op = o0 + oo;
            int s = op >> 6, oc = op & 63;
            size_t yi = (size_t)(b * 64 + oc) * K2 + s * 1024 + n0;
            __nv_bfloat16 h0 = __float2bfloat16(acc[oo][0]);
            __nv_bfloat16 h1 = __float2bfloat16(acc[oo][1]);
            __nv_bfloat16 l0 = __float2bfloat16(acc[oo][0] - __bfloat162float(h0));
            __nv_bfloat16 l1 = __float2bfloat16(acc[oo][1] - __bfloat162float(h1));
            *(__nv_bfloat162*)&g_yhi[yi] = __halves2bfloat162(h0, h1);
            *(__nv_bfloat162*)&g_ylo[yi] = __halves2bfloat162(l0, l1);
        }
    }
}

// ---------------------------------------------------------------------------
// GEMM: gc[m, w] = b_gc[m&63] + 3-pass split-bf16 mma.sync
// BM=128 BN=128 BK=64, XOR-swizzled smem (no pad), 3-stage cp.async,
// one __syncthreads per chunk, 96 chunks, 2 CTAs/SM.
// Row = 64 bf16 = 128 B = 8 x 16B units; unit j of row r stored at j^(r&7).
// ---------------------------------------------------------------------------
#define BM 128
#define BN 128
#define BK 64
#define ASTG (128 * 128)            // 16384 B per operand tile
#define STGB (2 * ASTG)             // 32768 B per stage
#define GDYN (3 * STGB)             // 98304 B

__device__ __forceinline__ void ldsm4(unsigned* r, unsigned addr) {
    asm volatile("ldmatrix.sync.aligned.m8n8.x4.shared.b16 {%0,%1,%2,%3}, [%4];"
                 : "=r"(r[0]), "=r"(r[1]), "=r"(r[2]), "=r"(r[3]) : "r"(addr));
}
__device__ __forceinline__ void mma16816(float* c, const unsigned* a,
                                         unsigned b0, unsigned b1) {
    asm volatile(
        "mma.sync.aligned.m16n8k16.row.col.f32.bf16.bf16.f32 "
        "{%0,%1,%2,%3}, {%4,%5,%6,%7}, {%8,%9}, {%0,%1,%2,%3};"
        : "+f"(c[0]), "+f"(c[1]), "+f"(c[2]), "+f"(c[3])
        : "r"(a[0]), "r"(a[1]), "r"(a[2]), "r"(a[3]), "r"(b0), "r"(b1));
}

__device__ __forceinline__ void load_chunk(unsigned base, int st, int t,
                                           int bm, int bn, int tid)
{
    int p = t >> 5;                  // pass 0..2
    int k0 = (t & 31) * BK;
    int s = k0 >> 10;
    int v0 = k0 & 1023;
    const __nv_bfloat16* Ap = (p == 1) ? g_ylo : g_yhi;
    const __nv_bfloat16* Bp = (p == 2) ? g_alo : g_ahi;
    unsigned ab = base + st * STGB;
    unsigned bb = ab + ASTG;
#pragma unroll
    for (int i = 0; i < 4; i++) {               // A: 1024 16B units
        int u2 = tid + i * 256;
        int row = u2 >> 3, j = u2 & 7;
        CP16(ab + row * 128 + ((j ^ (row & 7)) * 16),
             (const char*)(Ap + (size_t)(bm + row) * K2 + k0 + j * 8));
    }
#pragma unroll
    for (int i = 0; i < 4; i++) {               // B: 1024 16B units
        int u2 = tid + i * 256;
        int row = u2 >> 3, j = u2 & 7;
        CP16(bb + row * 128 + ((j ^ (row & 7)) * 16),
             (const char*)(Bp + (size_t)s * 1048576 +
                           (size_t)(bn + row) * 1024 + v0 + j * 8));
    }
    CP_COMMIT();
}

__global__ __launch_bounds__(256, 2) void k_gemm_mma(const float* __restrict__ b_gc)
{
    extern __shared__ __align__(16) char dsm[];
    unsigned base = s2u(dsm);

    int tid = threadIdx.x;
    int lane = tid & 31;
    int wid = tid >> 5;
    int wm = wid >> 1;        // 0..3 (32-row group)
    int wn = wid & 1;         // 0..1 (64-col group)
    int bm = blockIdx.y * BM;
    int bn = blockIdx.x * BN;

    float acc[2][8][4];
#pragma unroll
    for (int i = 0; i < 2; i++)
#pragma unroll
        for (int j = 0; j < 8; j++)
#pragma unroll
            for (int q = 0; q < 4; q++) acc[i][j][q] = 0.f;

    load_chunk(base, 0, 0, bm, bn, tid);
    load_chunk(base, 1, 1, bm, bn, tid);

    int st = 0;
    for (int t = 0; t < 96; t++) {
        if (t == 95) asm volatile("cp.async.wait_group 0;" ::: "memory");
        else         asm volatile("cp.async.wait_group 1;" ::: "memory");
        __syncthreads();

        if (t + 2 < 96) {
            int st2 = st + 2; if (st2 >= 3) st2 -= 3;
            load_chunk(base, st2, t + 2, bm, bn, tid);
        }

        unsigned abuf = base + st * STGB;
        unsigned bbuf = abuf + ASTG;

#pragma unroll
        for (int kk = 0; kk < 4; kk++) {
            unsigned ar[2][4];
#pragma unroll
            for (int mf = 0; mf < 2; mf++) {
                int mrow = wm * 32 + mf * 16 + (lane & 7) + ((lane >> 3) & 1) * 8;
                int uidx = kk * 2 + (lane >> 4);
                ldsm4(ar[mf], abuf + mrow * 128 + ((uidx ^ (mrow & 7)) * 16));
            }
            unsigned br[4][4];
#pragma unroll
            for (int nt = 0; nt < 4; nt++) {
                int nrow = wn * 64 + nt * 16 + (lane & 7) + (lane >> 4) * 8;
                int uidx = kk * 2 + ((lane >> 3) & 1);
                ldsm4(br[nt], bbuf + nrow * 128 + ((uidx ^ (nrow & 7)) * 16));
            }
#pragma unroll
            for (int mf = 0; mf < 2; mf++)
#pragma unroll
                for (int nt = 0; nt < 4; nt++) {
                    mma16816(acc[mf][nt * 2 + 0], ar[mf], br[nt][0], br[nt][1]);
                    mma16816(acc[mf][nt * 2 + 1], ar[mf], br[nt][2], br[nt][3]);
                }
        }
        st++; if (st >= 3) st = 0;
    }

    // epilogue: add bias, store fp32 to g_gc
#pragma unroll
    for (int mf = 0; mf < 2; mf++) {
        int r0 = bm + wm * 32 + mf * 16 + (lane >> 2);
        float bv0 = __ldg(&b_gc[r0 & 63]);
        float bv1 = __ldg(&b_gc[(r0 + 8) & 63]);
#pragma unroll
        for (int nf = 0; nf < 8; nf++) {
            int col = bn + wn * 64 + nf * 8 + (lane & 3) * 2;
            float* c4 = acc[mf][nf];
            *(float2*)&g_gc[(size_t)r0 * 1024 + col] =
                make_float2(c4[0] + bv0, c4[1] + bv0);
            *(float2*)&g_gc[(size_t)(r0 + 8) * 1024 + col] =
                make_float2(c4[2] + bv1, c4[3] + bv1);
        }
    }
}

// ---------------------------------------------------------------------------
// k_out: 128 thr/block, 512 blocks, 2 cols/thread, o-chunks of 16.
// ---------------------------------------------------------------------------
__global__ __launch_bounds__(128) void k_out(
    const float* __restrict__ h, const float* __restrict__ W_out,
    const float* __restrict__ b_out, const float* __restrict__ W_read,
    const float* __restrict__ b_read, const float* __restrict__ prelu_w,
    float* __restrict__ out)
{
    __shared__ float WoT[128][64];   // WoT[c][o]
    __shared__ float Wr[128];
    __shared__ float bo[64];
    for (int i = threadIdx.x; i < 64 * 128; i += 128) {
        int o = i >> 7, c = i & 127;
        WoT[c][o] = W_out[i];
    }
    Wr[threadIdx.x] = W_read[threadIdx.x];
    if (threadIdx.x < 64) bo[threadIdx.x] = b_out[threadIdx.x];
    __syncthreads();

    int b = blockIdx.x >> 2;
    int n0 = (blockIdx.x & 3) * 256 + threadIdx.x * 2;
    float pw = __ldg(prelu_w);
    float brd = __ldg(b_read);
    float racc[2] = {brd, brd};
    float* out2 = out + (size_t)Bb * Nn;

    for (int ch = 0; ch < 4; ch++) {
        int o0 = ch * 16;
        float acc[16][2];
#pragma unroll
        for (int oo = 0; oo < 16; oo++) {
            float bv = bo[o0 + oo];
            acc[oo][0] = bv; acc[oo][1] = bv;
        }
        for (int c = 0; c < 64; c++) {
            float2 g = *(const float2*)&g_gc[(size_t)(b * 64 + c) * 1024 + n0];
#pragma unroll
            for (int oo = 0; oo < 16; oo++) {
                float w = WoT[c][o0 + oo];
                acc[oo][0] = fmaf(w, g.x, acc[oo][0]);
                acc[oo][1] = fmaf(w, g.y, acc[oo][1]);
            }
        }
        for (int c = 0; c < 64; c++) {
            float2 hv = *(const float2*)&h[(size_t)(b * 64 + c) * 1024 + n0];
#pragma unroll
            for (int oo = 0; oo < 16; oo++) {
                float w = WoT[64 + c][o0 + oo];
                acc[oo][0] = fmaf(w, hv.x, acc[oo][0]);
                acc[oo][1] = fmaf(w, hv.y, acc[oo][1]);
            }
        }
#pragma unroll
        for (int oo = 0; oo < 16; oo++) {
            int o = o0 + oo;
            float wr = Wr[o];
            float2 p;
            p.x = acc[oo][0] >= 0.f ? acc[oo][0] : pw * acc[oo][0];
            p.y = acc[oo][1] >= 0.f ? acc[oo][1] : pw * acc[oo][1];
            *(float2*)&out2[(size_t)(b * 128 + o) * 1024 + n0] = p;
            racc[0] = fmaf(wr, p.x, racc[0]);
            racc[1] = fmaf(wr, p.y, racc[1]);
        }
    }

    for (int c = 0; c < 64; c++) {
        float2 hv = *(const float2*)&h[(size_t)(b * 64 + c) * 1024 + n0];
        *(float2*)&out2[(size_t)(b * 128 + 64 + c) * 1024 + n0] = hv;
        float wr = Wr[64 + c];
        racc[0] = fmaf(wr, hv.x, racc[0]);
        racc[1] = fmaf(wr, hv.y, racc[1]);
    }
    *(float2*)&out[(size_t)b * 1024 + n0] = make_float2(racc[0], racc[1]);
}

// ---------------------------------------------------------------------------
extern "C" void kernel_launch(void* const* d_in, const int* in_sizes, int n_in,
                              void* d_out, int out_size)
{
    const float* x      = (const float*)d_in[0];
    const float* m      = (const float*)d_in[1];
    const float* u      = (const float*)d_in[2];
    const float* h      = (const float*)d_in[3];
    const float* adj    = (const float*)d_in[4];
    const float* W_in   = (const float*)d_in[5];
    const float* b_in   = (const float*)d_in[6];
    const float* W_gc   = (const float*)d_in[7];
    const float* b_gc   = (const float*)d_in[8];
    const float* W_out  = (const float*)d_in[9];
    const float* b_out  = (const float*)d_in[10];
    const float* W_read = (const float*)d_in[11];
    const float* b_read = (const float*)d_in[12];
    const float* prelu  = (const float*)d_in[13];
    float* out = (float*)d_out;

    cudaFuncSetAttribute(k_gemm_mma, cudaFuncAttributeMaxDynamicSharedMemorySize, GDYN);

    k_adj<<<2048, 256>>>(adj);
    k_weff<<<1, 256>>>(W_in, b_in, W_gc);
    k_y<<<512, 128>>>(x, m, u, h);
    dim3 g(Nn / BN, (Bb * DMdim) / BM);   // (8, 64) = 512 CTAs
    k_gemm_mma<<<g, 256, GDYN>>>(b_gc);
    k_out<<<512, 128>>>(h, W_out, b_out, W_read, b_read, prelu, out);
}

// round 7
// speedup vs baseline: 1.5904x; 1.1147x over previous
#include <cuda_runtime.h>
#include <cuda_bf16.h>

#define Bb 128
#define Nn 1024
#define DMdim 64
#define K2 2048   // S * Nn

// Scratch (no allocs): static device globals
__device__ float g_gc[Bb * DMdim * Nn];                  // 32 MB
__device__ __nv_bfloat16 g_yhi[(size_t)8192 * 2048];     // 32 MB
__device__ __nv_bfloat16 g_ylo[(size_t)8192 * 2048];     // 32 MB
__device__ __nv_bfloat16 g_ahi[2 * 1024 * 1024];         // 4 MB
__device__ __nv_bfloat16 g_alo[2 * 1024 * 1024];         // 4 MB
__device__ float g_weff[128 * 68];
__device__ float g_beff[128];

// ---------------------------------------------------------------------------
__device__ __forceinline__ unsigned s2u(const void* p) {
    unsigned a;
    asm("{ .reg .u64 t; cvta.to.shared.u64 t, %1; cvt.u32.u64 %0, t; }"
        : "=r"(a) : "l"(p));
    return a;
}
#define CP16(dst, src) \
    asm volatile("cp.async.cg.shared.global [%0], [%1], 16;" :: "r"(dst), "l"(src))
#define CP_COMMIT() asm volatile("cp.async.commit_group;" ::: "memory")

// packed f32x2 helpers (FFMA2 path — B300 SASS, PTX-only)
__device__ __forceinline__ unsigned long long pack2(float a, float b) {
    unsigned long long r;
    asm("mov.b64 %0, {%1, %2};" : "=l"(r) : "f"(a), "f"(b));
    return r;
}
__device__ __forceinline__ unsigned long long bcast2(float a) {
    unsigned long long r;
    asm("mov.b64 %0, {%1, %1};" : "=l"(r) : "f"(a));
    return r;
}
__device__ __forceinline__ void ffma2(unsigned long long& d,
                                      unsigned long long a, unsigned long long b) {
    asm("fma.rn.f32x2 %0, %1, %2, %0;" : "+l"(d) : "l"(a), "l"(b));
}
__device__ __forceinline__ float2 unpack2(unsigned long long v) {
    float x, y;
    asm("mov.b64 {%0, %1}, %2;" : "=f"(x), "=f"(y) : "l"(v));
    return make_float2(x, y);
}

// ---------------------------------------------------------------------------
// split adj into hi/lo bf16
// ---------------------------------------------------------------------------
__global__ __launch_bounds__(256) void k_adj(const float* __restrict__ adj)
{
    int i = blockIdx.x * 256 + threadIdx.x;   // 524288 float4s
    float4 v = ((const float4*)adj)[i];
    __nv_bfloat16 h0 = __float2bfloat16(v.x);
    __nv_bfloat16 h1 = __float2bfloat16(v.y);
    __nv_bfloat16 h2 = __float2bfloat16(v.z);
    __nv_bfloat16 h3 = __float2bfloat16(v.w);
    __nv_bfloat16 l0 = __float2bfloat16(v.x - __bfloat162float(h0));
    __nv_bfloat16 l1 = __float2bfloat16(v.y - __bfloat162float(h1));
    __nv_bfloat16 l2 = __float2bfloat16(v.z - __bfloat162float(h2));
    __nv_bfloat16 l3 = __float2bfloat16(v.w - __bfloat162float(h3));
    ((__nv_bfloat162*)g_ahi)[i * 2 + 0] = __halves2bfloat162(h0, h1);
    ((__nv_bfloat162*)g_ahi)[i * 2 + 1] = __halves2bfloat162(h2, h3);
    ((__nv_bfloat162*)g_alo)[i * 2 + 0] = __halves2bfloat162(l0, l1);
    ((__nv_bfloat162*)g_alo)[i * 2 + 1] = __halves2bfloat162(l2, l3);
}

// ---------------------------------------------------------------------------
// fold W_in into W_gc:  W_eff[o'][c'] (o' in [0,128), c' in [0,68))
// ---------------------------------------------------------------------------
__global__ __launch_bounds__(256) void k_weff(
    const float* __restrict__ W_in, const float* __restrict__ b_in,
    const float* __restrict__ W_gc)
{
    int tid = threadIdx.x;
    for (int i = tid; i < 128 * 68; i += 256) {
        int op = i / 68, cp = i - op * 68;
        const float* wg = W_gc + (op & 63) * 128 + (op >> 6) * 64;
        float s = 0.f;
        for (int c = 0; c < 64; c++) s = fmaf(wg[c], W_in[c * 68 + cp], s);
        g_weff[i] = s;
    }
    if (tid < 128) {
        const float* wg = W_gc + (tid & 63) * 128 + (tid >> 6) * 64;
        float s = 0.f;
        for (int c = 0; c < 64; c++) s = fmaf(wg[c], b_in[c], s);
        g_beff[tid] = s;
    }
}

// ---------------------------------------------------------------------------
// k_y: FFMA2 version. 128 thr/block, 512 blocks, 2 cols/thread.
// Output-pair packing: WPs[c'][p] = (W_eff[2p][c'], W_eff[2p+1][c']).
// ---------------------------------------------------------------------------
__global__ __launch_bounds__(128) void k_y(
    const float* __restrict__ x, const float* __restrict__ m,
    const float* __restrict__ u, const float* __restrict__ h)
{
    __shared__ unsigned long long WPs[68][64];   // weight pairs
    __shared__ unsigned long long bep[64];       // bias pairs
    for (int i = threadIdx.x; i < 68 * 64; i += 128) {
        int cp = i >> 6, p = i & 63;
        WPs[cp][p] = pack2(g_weff[(2 * p) * 68 + cp], g_weff[(2 * p + 1) * 68 + cp]);
    }
    if (threadIdx.x < 64)
        bep[threadIdx.x] = pack2(g_beff[2 * threadIdx.x], g_beff[2 * threadIdx.x + 1]);
    __syncthreads();

    int b = blockIdx.x >> 2;
    int n0 = (blockIdx.x & 3) * 256 + threadIdx.x * 2;

    for (int ch = 0; ch < 8; ch++) {
        int p0 = ch * 8;                         // pair base (16 outputs)
        unsigned long long acc[8][2];
#pragma unroll
        for (int i = 0; i < 8; i++) { acc[i][0] = bep[p0 + i]; acc[i][1] = bep[p0 + i]; }

#define YACC(cp, ptr) do {                                                     \
        float2 _v = *(const float2*)(ptr);                                     \
        unsigned long long _vx = bcast2(_v.x), _vy = bcast2(_v.y);             \
        _Pragma("unroll")                                                      \
        for (int i = 0; i < 8; i++) {                                          \
            unsigned long long _wp = WPs[cp][p0 + i];                          \
            ffma2(acc[i][0], _wp, _vx);                                        \
            ffma2(acc[i][1], _wp, _vy);                                        \
        }                                                                      \
    } while (0)

        YACC(0, &x[b * 1024 + n0]);
        YACC(1, &m[b * 1024 + n0]);
        YACC(2, &u[b * 2048 + n0]);
        YACC(3, &u[b * 2048 + 1024 + n0]);
        for (int c = 0; c < 64; c++)
            YACC(4 + c, &h[(b * 64 + c) * 1024 + n0]);
#undef YACC

#pragma unroll
        for (int i = 0; i < 8; i++) {
            float2 u0 = unpack2(acc[i][0]);      // (out_{2i}(n0),   out_{2i+1}(n0))
            float2 u1 = unpack2(acc[i][1]);      // (out_{2i}(n0+1), out_{2i+1}(n0+1))
#pragma unroll
            for (int q = 0; q < 2; q++) {
                int op = ch * 16 + 2 * i + q;
                float v0 = q ? u0.y : u0.x;
                float v1 = q ? u1.y : u1.x;
                int s = op >> 6, oc = op & 63;
                size_t yi = (size_t)(b * 64 + oc) * K2 + s * 1024 + n0;
                __nv_bfloat16 h0 = __float2bfloat16(v0);
                __nv_bfloat16 h1 = __float2bfloat16(v1);
                __nv_bfloat16 l0 = __float2bfloat16(v0 - __bfloat162float(h0));
                __nv_bfloat16 l1 = __float2bfloat16(v1 - __bfloat162float(h1));
                *(__nv_bfloat162*)&g_yhi[yi] = __halves2bfloat162(h0, h1);
                *(__nv_bfloat162*)&g_ylo[yi] = __halves2bfloat162(l0, l1);
            }
        }
    }
}

// ---------------------------------------------------------------------------
// GEMM (unchanged from R6 — proven 272 µs): 3-pass split-bf16 mma.sync,
// BM=128 BN=128 BK=64, XOR-swizzled smem, 3-stage cp.async, 2 CTAs/SM.
// ---------------------------------------------------------------------------
#define BM 128
#define BN 128
#define BK 64
#define ASTG (128 * 128)
#define STGB (2 * ASTG)
#define GDYN (3 * STGB)

__device__ __forceinline__ void ldsm4(unsigned* r, unsigned addr) {
    asm volatile("ldmatrix.sync.aligned.m8n8.x4.shared.b16 {%0,%1,%2,%3}, [%4];"
                 : "=r"(r[0]), "=r"(r[1]), "=r"(r[2]), "=r"(r[3]) : "r"(addr));
}
__device__ __forceinline__ void mma16816(float* c, const unsigned* a,
                                         unsigned b0, unsigned b1) {
    asm volatile(
        "mma.sync.aligned.m16n8k16.row.col.f32.bf16.bf16.f32 "
        "{%0,%1,%2,%3}, {%4,%5,%6,%7}, {%8,%9}, {%0,%1,%2,%3};"
        : "+f"(c[0]), "+f"(c[1]), "+f"(c[2]), "+f"(c[3])
        : "r"(a[0]), "r"(a[1]), "r"(a[2]), "r"(a[3]), "r"(b0), "r"(b1));
}

__device__ __forceinline__ void load_chunk(unsigned base, int st, int t,
                                           int bm, int bn, int tid)
{
    int p = t >> 5;
    int k0 = (t & 31) * BK;
    int s = k0 >> 10;
    int v0 = k0 & 1023;
    const __nv_bfloat16* Ap = (p == 1) ? g_ylo : g_yhi;
    const __nv_bfloat16* Bp = (p == 2) ? g_alo : g_ahi;
    unsigned ab = base + st * STGB;
    unsigned bb = ab + ASTG;
#pragma unroll
    for (int i = 0; i < 4; i++) {
        int u2 = tid + i * 256;
        int row = u2 >> 3, j = u2 & 7;
        CP16(ab + row * 128 + ((j ^ (row & 7)) * 16),
             (const char*)(Ap + (size_t)(bm + row) * K2 + k0 + j * 8));
    }
#pragma unroll
    for (int i = 0; i < 4; i++) {
        int u2 = tid + i * 256;
        int row = u2 >> 3, j = u2 & 7;
        CP16(bb + row * 128 + ((j ^ (row & 7)) * 16),
             (const char*)(Bp + (size_t)s * 1048576 +
                           (size_t)(bn + row) * 1024 + v0 + j * 8));
    }
    CP_COMMIT();
}

__global__ __launch_bounds__(256, 2) void k_gemm_mma(const float* __restrict__ b_gc)
{
    extern __shared__ __align__(16) char dsm[];
    unsigned base = s2u(dsm);

    int tid = threadIdx.x;
    int lane = tid & 31;
    int wid = tid >> 5;
    int wm = wid >> 1;
    int wn = wid & 1;
    int bm = blockIdx.y * BM;
    int bn = blockIdx.x * BN;

    float acc[2][8][4];
#pragma unroll
    for (int i = 0; i < 2; i++)
#pragma unroll
        for (int j = 0; j < 8; j++)
#pragma unroll
            for (int q = 0; q < 4; q++) acc[i][j][q] = 0.f;

    load_chunk(base, 0, 0, bm, bn, tid);
    load_chunk(base, 1, 1, bm, bn, tid);

    int st = 0;
    for (int t = 0; t < 96; t++) {
        if (t == 95) asm volatile("cp.async.wait_group 0;" ::: "memory");
        else         asm volatile("cp.async.wait_group 1;" ::: "memory");
        __syncthreads();

        if (t + 2 < 96) {
            int st2 = st + 2; if (st2 >= 3) st2 -= 3;
            load_chunk(base, st2, t + 2, bm, bn, tid);
        }

        unsigned abuf = base + st * STGB;
        unsigned bbuf = abuf + ASTG;

#pragma unroll
        for (int kk = 0; kk < 4; kk++) {
            unsigned ar[2][4];
#pragma unroll
            for (int mf = 0; mf < 2; mf++) {
                int mrow = wm * 32 + mf * 16 + (lane & 7) + ((lane >> 3) & 1) * 8;
                int uidx = kk * 2 + (lane >> 4);
                ldsm4(ar[mf], abuf + mrow * 128 + ((uidx ^ (mrow & 7)) * 16));
            }
            unsigned br[4][4];
#pragma unroll
            for (int nt = 0; nt < 4; nt++) {
                int nrow = wn * 64 + nt * 16 + (lane & 7) + (lane >> 4) * 8;
                int uidx = kk * 2 + ((lane >> 3) & 1);
                ldsm4(br[nt], bbuf + nrow * 128 + ((uidx ^ (nrow & 7)) * 16));
            }
#pragma unroll
            for (int mf = 0; mf < 2; mf++)
#pragma unroll
                for (int nt = 0; nt < 4; nt++) {
                    mma16816(acc[mf][nt * 2 + 0], ar[mf], br[nt][0], br[nt][1]);
                    mma16816(acc[mf][nt * 2 + 1], ar[mf], br[nt][2], br[nt][3]);
                }
        }
        st++; if (st >= 3) st = 0;
    }

#pragma unroll
    for (int mf = 0; mf < 2; mf++) {
        int r0 = bm + wm * 32 + mf * 16 + (lane >> 2);
        float bv0 = __ldg(&b_gc[r0 & 63]);
        float bv1 = __ldg(&b_gc[(r0 + 8) & 63]);
#pragma unroll
        for (int nf = 0; nf < 8; nf++) {
            int col = bn + wn * 64 + nf * 8 + (lane & 3) * 2;
            float* c4 = acc[mf][nf];
            *(float2*)&g_gc[(size_t)r0 * 1024 + col] =
                make_float2(c4[0] + bv0, c4[1] + bv0);
            *(float2*)&g_gc[(size_t)(r0 + 8) * 1024 + col] =
                make_float2(c4[2] + bv1, c4[3] + bv1);
        }
    }
}

// ---------------------------------------------------------------------------
// k_out: FFMA2 version. 128 thr/block, 512 blocks, 2 cols/thread.
// Weight pairs over o: WoPs[c][p] = (W_out[2p][c], W_out[2p+1][c]).
// ---------------------------------------------------------------------------
__global__ __launch_bounds__(128) void k_out(
    const float* __restrict__ h, const float* __restrict__ W_out,
    const float* __restrict__ b_out, const float* __restrict__ W_read,
    const float* __restrict__ b_read, const float* __restrict__ prelu_w,
    float* __restrict__ out)
{
    __shared__ unsigned long long WoPs[128][32];
    __shared__ unsigned long long bop[32];
    __shared__ float Wr[128];
    for (int i = threadIdx.x; i < 128 * 32; i += 128) {
        int c = i >> 5, p = i & 31;
        WoPs[c][p] = pack2(W_out[(2 * p) * 128 + c], W_out[(2 * p + 1) * 128 + c]);
    }
    Wr[threadIdx.x] = W_read[threadIdx.x];
    if (threadIdx.x < 32)
        bop[threadIdx.x] = pack2(b_out[2 * threadIdx.x], b_out[2 * threadIdx.x + 1]);
    __syncthreads();

    int b = blockIdx.x >> 2;
    int n0 = (blockIdx.x & 3) * 256 + threadIdx.x * 2;
    float pw = __ldg(prelu_w);
    float brd = __ldg(b_read);
    float racc[2] = {brd, brd};
    float* out2 = out + (size_t)Bb * Nn;

    for (int ch = 0; ch < 4; ch++) {
        int p0 = ch * 8;                          // 16 outputs = 8 pairs
        unsigned long long acc[8][2];
#pragma unroll
        for (int i = 0; i < 8; i++) { acc[i][0] = bop[p0 + i]; acc[i][1] = bop[p0 + i]; }

        for (int c = 0; c < 64; c++) {
            float2 g = *(const float2*)&g_gc[(size_t)(b * 64 + c) * 1024 + n0];
            unsigned long long vx = bcast2(g.x), vy = bcast2(g.y);
#pragma unroll
            for (int i = 0; i < 8; i++) {
                unsigned long long wp = WoPs[c][p0 + i];
                ffma2(acc[i][0], wp, vx);
                ffma2(acc[i][1], wp, vy);
            }
        }
        for (int c = 0; c < 64; c++) {
            float2 hv = *(const float2*)&h[(size_t)(b * 64 + c) * 1024 + n0];
            unsigned long long vx = bcast2(hv.x), vy = bcast2(hv.y);
#pragma unroll
            for (int i = 0; i < 8; i++) {
                unsigned long long wp = WoPs[64 + c][p0 + i];
                ffma2(acc[i][0], wp, vx);
                ffma2(acc[i][1], wp, vy);
            }
        }

#pragma unroll
        for (int i = 0; i < 8; i++) {
            float2 u0 = unpack2(acc[i][0]);
            float2 u1 = unpack2(acc[i][1]);
#pragma unroll
            for (int q = 0; q < 2; q++) {
                int o = ch * 16 + 2 * i + q;
                float v0 = q ? u0.y : u0.x;
                float v1 = q ? u1.y : u1.x;
                float p0v = v0 >= 0.f ? v0 : pw * v0;
                float p1v = v1 >= 0.f ? v1 : pw * v1;
                *(float2*)&out2[(size_t)(b * 128 + o) * 1024 + n0] =
                    make_float2(p0v, p1v);
                float wr = Wr[o];
                racc[0] = fmaf(wr, p0v, racc[0]);
                racc[1] = fmaf(wr, p1v, racc[1]);
            }
        }
    }

    for (int c = 0; c < 64; c++) {
        float2 hv = *(const float2*)&h[(size_t)(b * 64 + c) * 1024 + n0];
        *(float2*)&out2[(size_t)(b * 128 + 64 + c) * 1024 + n0] = hv;
        float wr = Wr[64 + c];
        racc[0] = fmaf(wr, hv.x, racc[0]);
        racc[1] = fmaf(wr, hv.y, racc[1]);
    }
    *(float2*)&out[(size_t)b * 1024 + n0] = make_float2(racc[0], racc[1]);
}

// ---------------------------------------------------------------------------
extern "C" void kernel_launch(void* const* d_in, const int* in_sizes, int n_in,
                              void* d_out, int out_size)
{
    const float* x      = (const float*)d_in[0];
    const float* m      = (const float*)d_in[1];
    const float* u      = (const float*)d_in[2];
    const float* h      = (const float*)d_in[3];
    const float* adj    = (const float*)d_in[4];
    const float* W_in   = (const float*)d_in[5];
    const float* b_in   = (const float*)d_in[6];
    const float* W_gc   = (const float*)d_in[7];
    const float* b_gc   = (const float*)d_in[8];
    const float* W_out  = (const float*)d_in[9];
    const float* b_out  = (const float*)d_in[10];
    const float* W_read = (const float*)d_in[11];
    const float* b_read = (const float*)d_in[12];
    const float* prelu  = (const float*)d_in[13];
    float* out = (float*)d_out;

    cudaFuncSetAttribute(k_gemm_mma, cudaFuncAttributeMaxDynamicSharedMemorySize, GDYN);

    k_adj<<<2048, 256>>>(adj);
    k_weff<<<1, 256>>>(W_in, b_in, W_gc);
    k_y<<<512, 128>>>(x, m, u, h);
    dim3 g(Nn / BN, (Bb * DMdim) / BM);   // (8, 64) = 512 CTAs
    k_gemm_mma<<<g, 256, GDYN>>>(b_gc);
    k_out<<<512, 128>>>(h, W_out, b_out, W_read, b_read, prelu, out);
}

// round 8
// speedup vs baseline: 1.8173x; 1.1427x over previous
#include <cuda_runtime.h>
#include <cuda_bf16.h>

#define Bb 128
#define Nn 1024
#define DMdim 64
#define K2 2048   // S * Nn

// Scratch (no allocs): static device globals
__device__ float g_gc[Bb * DMdim * Nn];                  // 32 MB
__device__ __nv_bfloat16 g_yhi[(size_t)8192 * 2048];     // 32 MB
__device__ __nv_bfloat16 g_ylo[(size_t)8192 * 2048];     // 32 MB
__device__ __nv_bfloat16 g_ahi[2 * 1024 * 1024];         // 4 MB
__device__ float g_weff[128 * 68];
__device__ float g_beff[128];

// ---------------------------------------------------------------------------
__device__ __forceinline__ unsigned s2u(const void* p) {
    unsigned a;
    asm("{ .reg .u64 t; cvta.to.shared.u64 t, %1; cvt.u32.u64 %0, t; }"
        : "=r"(a) : "l"(p));
    return a;
}
#define CP16(dst, src) \
    asm volatile("cp.async.cg.shared.global [%0], [%1], 16;" :: "r"(dst), "l"(src))
#define CP_COMMIT() asm volatile("cp.async.commit_group;" ::: "memory")

// packed f32x2 helpers (FFMA2 path — B300 SASS, PTX-only)
__device__ __forceinline__ unsigned long long pack2(float a, float b) {
    unsigned long long r;
    asm("mov.b64 %0, {%1, %2};" : "=l"(r) : "f"(a), "f"(b));
    return r;
}
__device__ __forceinline__ unsigned long long bcast2(float a) {
    unsigned long long r;
    asm("mov.b64 %0, {%1, %1};" : "=l"(r) : "f"(a));
    return r;
}
__device__ __forceinline__ void ffma2(unsigned long long& d,
                                      unsigned long long a, unsigned long long b) {
    asm("fma.rn.f32x2 %0, %1, %2, %0;" : "+l"(d) : "l"(a), "l"(b));
}
__device__ __forceinline__ float2 unpack2(unsigned long long v) {
    float x, y;
    asm("mov.b64 {%0, %1}, %2;" : "=f"(x), "=f"(y) : "l"(v));
    return make_float2(x, y);
}

// ---------------------------------------------------------------------------
// adj -> hi bf16 only (lo pass dropped)
// ---------------------------------------------------------------------------
__global__ __launch_bounds__(256) void k_adj(const float* __restrict__ adj)
{
    int i = blockIdx.x * 256 + threadIdx.x;   // 524288 float4s
    float4 v = ((const float4*)adj)[i];
    __nv_bfloat16 h0 = __float2bfloat16(v.x);
    __nv_bfloat16 h1 = __float2bfloat16(v.y);
    __nv_bfloat16 h2 = __float2bfloat16(v.z);
    __nv_bfloat16 h3 = __float2bfloat16(v.w);
    ((__nv_bfloat162*)g_ahi)[i * 2 + 0] = __halves2bfloat162(h0, h1);
    ((__nv_bfloat162*)g_ahi)[i * 2 + 1] = __halves2bfloat162(h2, h3);
}

// ---------------------------------------------------------------------------
// fold W_in into W_gc:  W_eff[o'][c'] (o' in [0,128), c' in [0,68))
// ---------------------------------------------------------------------------
__global__ __launch_bounds__(256) void k_weff(
    const float* __restrict__ W_in, const float* __restrict__ b_in,
    const float* __restrict__ W_gc)
{
    int tid = threadIdx.x;
    for (int i = tid; i < 128 * 68; i += 256) {
        int op = i / 68, cp = i - op * 68;
        const float* wg = W_gc + (op & 63) * 128 + (op >> 6) * 64;
        float s = 0.f;
        for (int c = 0; c < 64; c++) s = fmaf(wg[c], W_in[c * 68 + cp], s);
        g_weff[i] = s;
    }
    if (tid < 128) {
        const float* wg = W_gc + (tid & 63) * 128 + (tid >> 6) * 64;
        float s = 0.f;
        for (int c = 0; c < 64; c++) s = fmaf(wg[c], b_in[c], s);
        g_beff[tid] = s;
    }
}

// ---------------------------------------------------------------------------
// k_y: FFMA2, 4 cols/thread, 128 thr/block, 256 blocks.
// ---------------------------------------------------------------------------
__global__ __launch_bounds__(128) void k_y(
    const float* __restrict__ x, const float* __restrict__ m,
    const float* __restrict__ u, const float* __restrict__ h)
{
    __shared__ unsigned long long WPs[68][64];   // weight pairs
    __shared__ unsigned long long bep[64];       // bias pairs
    for (int i = threadIdx.x; i < 68 * 64; i += 128) {
        int cp = i >> 6, p = i & 63;
        WPs[cp][p] = pack2(g_weff[(2 * p) * 68 + cp], g_weff[(2 * p + 1) * 68 + cp]);
    }
    if (threadIdx.x < 64)
        bep[threadIdx.x] = pack2(g_beff[2 * threadIdx.x], g_beff[2 * threadIdx.x + 1]);
    __syncthreads();

    int b = blockIdx.x >> 1;
    int n0 = (blockIdx.x & 1) * 512 + threadIdx.x * 4;

    for (int ch = 0; ch < 8; ch++) {
        int p0 = ch * 8;                         // pair base (16 outputs)
        unsigned long long acc[8][4];
#pragma unroll
        for (int i = 0; i < 8; i++) {
            unsigned long long bv = bep[p0 + i];
            acc[i][0] = bv; acc[i][1] = bv; acc[i][2] = bv; acc[i][3] = bv;
        }

#define YACC(cp, ptr) do {                                                     \
        float4 _v = *(const float4*)(ptr);                                     \
        unsigned long long _v0 = bcast2(_v.x), _v1 = bcast2(_v.y);             \
        unsigned long long _v2 = bcast2(_v.z), _v3 = bcast2(_v.w);             \
        _Pragma("unroll")                                                      \
        for (int i = 0; i < 8; i++) {                                          \
            unsigned long long _wp = WPs[cp][p0 + i];                          \
            ffma2(acc[i][0], _wp, _v0);                                        \
            ffma2(acc[i][1], _wp, _v1);                                        \
            ffma2(acc[i][2], _wp, _v2);                                        \
            ffma2(acc[i][3], _wp, _v3);                                        \
        }                                                                      \
    } while (0)

        YACC(0, &x[b * 1024 + n0]);
        YACC(1, &m[b * 1024 + n0]);
        YACC(2, &u[b * 2048 + n0]);
        YACC(3, &u[b * 2048 + 1024 + n0]);
        for (int c = 0; c < 64; c++)
            YACC(4 + c, &h[(b * 64 + c) * 1024 + n0]);
#undef YACC

#pragma unroll
        for (int i = 0; i < 8; i++) {
            float2 c0 = unpack2(acc[i][0]);  // (o=2i, n0) , (o=2i+1, n0)
            float2 c1 = unpack2(acc[i][1]);
            float2 c2 = unpack2(acc[i][2]);
            float2 c3 = unpack2(acc[i][3]);
#pragma unroll
            for (int q = 0; q < 2; q++) {
                int op = ch * 16 + 2 * i + q;
                float v0 = q ? c0.y : c0.x;
                float v1 = q ? c1.y : c1.x;
                float v2 = q ? c2.y : c2.x;
                float v3 = q ? c3.y : c3.x;
                int s = op >> 6, oc = op & 63;
                size_t yi = (size_t)(b * 64 + oc) * K2 + s * 1024 + n0;
                __nv_bfloat16 h0 = __float2bfloat16(v0);
                __nv_bfloat16 h1 = __float2bfloat16(v1);
                __nv_bfloat16 h2 = __float2bfloat16(v2);
                __nv_bfloat16 h3 = __float2bfloat16(v3);
                __nv_bfloat162 hp0 = __halves2bfloat162(h0, h1);
                __nv_bfloat162 hp1 = __halves2bfloat162(h2, h3);
                uint2 hw; hw.x = *(unsigned*)&hp0; hw.y = *(unsigned*)&hp1;
                *(uint2*)&g_yhi[yi] = hw;
                __nv_bfloat162 lp0 = __halves2bfloat162(
                    __float2bfloat16(v0 - __bfloat162float(h0)),
                    __float2bfloat16(v1 - __bfloat162float(h1)));
                __nv_bfloat162 lp1 = __halves2bfloat162(
                    __float2bfloat16(v2 - __bfloat162float(h2)),
                    __float2bfloat16(v3 - __bfloat162float(h3)));
                uint2 lw; lw.x = *(unsigned*)&lp0; lw.y = *(unsigned*)&lp1;
                *(uint2*)&g_ylo[yi] = lw;
            }
        }
    }
}

// ---------------------------------------------------------------------------
// GEMM: 2-pass split-bf16 mma.sync  gc = (yhi + ylo) @ ahi  (+ bias)
// BM=128 BN=128 BK=64, XOR-swizzled smem, 3-stage cp.async, 2 CTAs/SM.
// ---------------------------------------------------------------------------
#define BM 128
#define BN 128
#define BK 64
#define ASTG (128 * 128)
#define STGB (2 * ASTG)
#define GDYN (3 * STGB)
#define NCHK 64

__device__ __forceinline__ void ldsm4(unsigned* r, unsigned addr) {
    asm volatile("ldmatrix.sync.aligned.m8n8.x4.shared.b16 {%0,%1,%2,%3}, [%4];"
                 : "=r"(r[0]), "=r"(r[1]), "=r"(r[2]), "=r"(r[3]) : "r"(addr));
}
__device__ __forceinline__ void mma16816(float* c, const unsigned* a,
                                         unsigned b0, unsigned b1) {
    asm volatile(
        "mma.sync.aligned.m16n8k16.row.col.f32.bf16.bf16.f32 "
        "{%0,%1,%2,%3}, {%4,%5,%6,%7}, {%8,%9}, {%0,%1,%2,%3};"
        : "+f"(c[0]), "+f"(c[1]), "+f"(c[2]), "+f"(c[3])
        : "r"(a[0]), "r"(a[1]), "r"(a[2]), "r"(a[3]), "r"(b0), "r"(b1));
}

__device__ __forceinline__ void load_chunk(unsigned base, int st, int t,
                                           int bm, int bn, int tid)
{
    int p = t >> 5;                  // pass 0..1
    int k0 = (t & 31) * BK;
    int s = k0 >> 10;
    int v0 = k0 & 1023;
    const __nv_bfloat16* Ap = p ? g_ylo : g_yhi;
    unsigned ab = base + st * STGB;
    unsigned bb = ab + ASTG;
#pragma unroll
    for (int i = 0; i < 4; i++) {
        int u2 = tid + i * 256;
        int row = u2 >> 3, j = u2 & 7;
        CP16(ab + row * 128 + ((j ^ (row & 7)) * 16),
             (const char*)(Ap + (size_t)(bm + row) * K2 + k0 + j * 8));
    }
#pragma unroll
    for (int i = 0; i < 4; i++) {
        int u2 = tid + i * 256;
        int row = u2 >> 3, j = u2 & 7;
        CP16(bb + row * 128 + ((j ^ (row & 7)) * 16),
             (const char*)(g_ahi + (size_t)s * 1048576 +
                           (size_t)(bn + row) * 1024 + v0 + j * 8));
    }
    CP_COMMIT();
}

__global__ __launch_bounds__(256, 2) void k_gemm_mma(const float* __restrict__ b_gc)
{
    extern __shared__ __align__(16) char dsm[];
    unsigned base = s2u(dsm);

    int tid = threadIdx.x;
    int lane = tid & 31;
    int wid = tid >> 5;
    int wm = wid >> 1;
    int wn = wid & 1;
    int bm = blockIdx.y * BM;
    int bn = blockIdx.x * BN;

    float acc[2][8][4];
#pragma unroll
    for (int i = 0; i < 2; i++)
#pragma unroll
        for (int j = 0; j < 8; j++)
#pragma unroll
            for (int q = 0; q < 4; q++) acc[i][j][q] = 0.f;

    load_chunk(base, 0, 0, bm, bn, tid);
    load_chunk(base, 1, 1, bm, bn, tid);

    int st = 0;
    for (int t = 0; t < NCHK; t++) {
        if (t == NCHK - 1) asm volatile("cp.async.wait_group 0;" ::: "memory");
        else               asm volatile("cp.async.wait_group 1;" ::: "memory");
        __syncthreads();

        if (t + 2 < NCHK) {
            int st2 = st + 2; if (st2 >= 3) st2 -= 3;
            load_chunk(base, st2, t + 2, bm, bn, tid);
        }

        unsigned abuf = base + st * STGB;
        unsigned bbuf = abuf + ASTG;

#pragma unroll
        for (int kk = 0; kk < 4; kk++) {
            unsigned ar[2][4];
#pragma unroll
            for (int mf = 0; mf < 2; mf++) {
                int mrow = wm * 32 + mf * 16 + (lane & 7) + ((lane >> 3) & 1) * 8;
                int uidx = kk * 2 + (lane >> 4);
                ldsm4(ar[mf], abuf + mrow * 128 + ((uidx ^ (mrow & 7)) * 16));
            }
            unsigned br[4][4];
#pragma unroll
            for (int nt = 0; nt < 4; nt++) {
                int nrow = wn * 64 + nt * 16 + (lane & 7) + (lane >> 4) * 8;
                int uidx = kk * 2 + ((lane >> 3) & 1);
                ldsm4(br[nt], bbuf + nrow * 128 + ((uidx ^ (nrow & 7)) * 16));
            }
#pragma unroll
            for (int mf = 0; mf < 2; mf++)
#pragma unroll
                for (int nt = 0; nt < 4; nt++) {
                    mma16816(acc[mf][nt * 2 + 0], ar[mf], br[nt][0], br[nt][1]);
                    mma16816(acc[mf][nt * 2 + 1], ar[mf], br[nt][2], br[nt][3]);
                }
        }
        st++; if (st >= 3) st = 0;
    }

#pragma unroll
    for (int mf = 0; mf < 2; mf++) {
        int r0 = bm + wm * 32 + mf * 16 + (lane >> 2);
        float bv0 = __ldg(&b_gc[r0 & 63]);
        float bv1 = __ldg(&b_gc[(r0 + 8) & 63]);
#pragma unroll
        for (int nf = 0; nf < 8; nf++) {
            int col = bn + wn * 64 + nf * 8 + (lane & 3) * 2;
            float* c4 = acc[mf][nf];
            *(float2*)&g_gc[(size_t)r0 * 1024 + col] =
                make_float2(c4[0] + bv0, c4[1] + bv0);
            *(float2*)&g_gc[(size_t)(r0 + 8) * 1024 + col] =
                make_float2(c4[2] + bv1, c4[3] + bv1);
        }
    }
}

// ---------------------------------------------------------------------------
// k_out: FFMA2, 4 cols/thread, 128 thr/block, 256 blocks.
// ---------------------------------------------------------------------------
__global__ __launch_bounds__(128) void k_out(
    const float* __restrict__ h, const float* __restrict__ W_out,
    const float* __restrict__ b_out, const float* __restrict__ W_read,
    const float* __restrict__ b_read, const float* __restrict__ prelu_w,
    float* __restrict__ out)
{
    __shared__ unsigned long long WoPs[128][32];
    __shared__ unsigned long long bop[32];
    __shared__ float Wr[128];
    for (int i = threadIdx.x; i < 128 * 32; i += 128) {
        int c = i >> 5, p = i & 31;
        WoPs[c][p] = pack2(W_out[(2 * p) * 128 + c], W_out[(2 * p + 1) * 128 + c]);
    }
    Wr[threadIdx.x] = W_read[threadIdx.x];
    if (threadIdx.x < 32)
        bop[threadIdx.x] = pack2(b_out[2 * threadIdx.x], b_out[2 * threadIdx.x + 1]);
    __syncthreads();

    int b = blockIdx.x >> 1;
    int n0 = (blockIdx.x & 1) * 512 + threadIdx.x * 4;
    float pw = __ldg(prelu_w);
    float brd = __ldg(b_read);
    float racc[4] = {brd, brd, brd, brd};
    float* out2 = out + (size_t)Bb * Nn;

    for (int ch = 0; ch < 4; ch++) {
        int p0 = ch * 8;                          // 16 outputs = 8 pairs
        unsigned long long acc[8][4];
#pragma unroll
        for (int i = 0; i < 8; i++) {
            unsigned long long bv = bop[p0 + i];
            acc[i][0] = bv; acc[i][1] = bv; acc[i][2] = bv; acc[i][3] = bv;
        }

        for (int c = 0; c < 64; c++) {
            float4 g = *(const float4*)&g_gc[(size_t)(b * 64 + c) * 1024 + n0];
            unsigned long long v0 = bcast2(g.x), v1 = bcast2(g.y);
            unsigned long long v2 = bcast2(g.z), v3 = bcast2(g.w);
#pragma unroll
            for (int i = 0; i < 8; i++) {
                unsigned long long wp = WoPs[c][p0 + i];
                ffma2(acc[i][0], wp, v0);
                ffma2(acc[i][1], wp, v1);
                ffma2(acc[i][2], wp, v2);
                ffma2(acc[i][3], wp, v3);
            }
        }
        for (int c = 0; c < 64; c++) {
            float4 hv = *(const float4*)&h[(size_t)(b * 64 + c) * 1024 + n0];
            unsigned long long v0 = bcast2(hv.x), v1 = bcast2(hv.y);
            unsigned long long v2 = bcast2(hv.z), v3 = bcast2(hv.w);
#pragma unroll
            for (int i = 0; i < 8; i++) {
                unsigned long long wp = WoPs[64 + c][p0 + i];
                ffma2(acc[i][0], wp, v0);
                ffma2(acc[i][1], wp, v1);
                ffma2(acc[i][2], wp, v2);
                ffma2(acc[i][3], wp, v3);
            }
        }

#pragma unroll
        for (int i = 0; i < 8; i++) {
            float2 c0 = unpack2(acc[i][0]);
            float2 c1 = unpack2(acc[i][1]);
            float2 c2 = unpack2(acc[i][2]);
            float2 c3 = unpack2(acc[i][3]);
#pragma unroll
            for (int q = 0; q < 2; q++) {
                int o = ch * 16 + 2 * i + q;
                float v0 = q ? c0.y : c0.x;
                float v1 = q ? c1.y : c1.x;
                float v2 = q ? c2.y : c2.x;
                float v3 = q ? c3.y : c3.x;
                float4 p;
                p.x = v0 >= 0.f ? v0 : pw * v0;
                p.y = v1 >= 0.f ? v1 : pw * v1;
                p.z = v2 >= 0.f ? v2 : pw * v2;
                p.w = v3 >= 0.f ? v3 : pw * v3;
                *(float4*)&out2[(size_t)(b * 128 + o) * 1024 + n0] = p;
                float wr = Wr[o];
                racc[0] = fmaf(wr, p.x, racc[0]);
                racc[1] = fmaf(wr, p.y, racc[1]);
                racc[2] = fmaf(wr, p.z, racc[2]);
                racc[3] = fmaf(wr, p.w, racc[3]);
            }
        }
    }

    for (int c = 0; c < 64; c++) {
        float4 hv = *(const float4*)&h[(size_t)(b * 64 + c) * 1024 + n0];
        *(float4*)&out2[(size_t)(b * 128 + 64 + c) * 1024 + n0] = hv;
        float wr = Wr[64 + c];
        racc[0] = fmaf(wr, hv.x, racc[0]);
        racc[1] = fmaf(wr, hv.y, racc[1]);
        racc[2] = fmaf(wr, hv.z, racc[2]);
        racc[3] = fmaf(wr, hv.w, racc[3]);
    }
    *(float4*)&out[(size_t)b * 1024 + n0] =
        make_float4(racc[0], racc[1], racc[2], racc[3]);
}

// ---------------------------------------------------------------------------
extern "C" void kernel_launch(void* const* d_in, const int* in_sizes, int n_in,
                              void* d_out, int out_size)
{
    const float* x      = (const float*)d_in[0];
    const float* m      = (const float*)d_in[1];
    const float* u      = (const float*)d_in[2];
    const float* h      = (const float*)d_in[3];
    const float* adj    = (const float*)d_in[4];
    const float* W_in   = (const float*)d_in[5];
    const float* b_in   = (const float*)d_in[6];
    const float* W_gc   = (const float*)d_in[7];
    const float* b_gc   = (const float*)d_in[8];
    const float* W_out  = (const float*)d_in[9];
    const float* b_out  = (const float*)d_in[10];
    const float* W_read = (const float*)d_in[11];
    const float* b_read = (const float*)d_in[12];
    const float* prelu  = (const float*)d_in[13];
    float* out = (float*)d_out;

    cudaFuncSetAttribute(k_gemm_mma, cudaFuncAttributeMaxDynamicSharedMemorySize, GDYN);

    k_adj<<<2048, 256>>>(adj);
    k_weff<<<1, 256>>>(W_in, b_in, W_gc);
    k_y<<<256, 128>>>(x, m, u, h);
    dim3 g(Nn / BN, (Bb * DMdim) / BM);   // (8, 64) = 512 CTAs
    k_gemm_mma<<<g, 256, GDYN>>>(b_gc);
    k_out<<<256, 128>>>(h, W_out, b_out, W_read, b_read, prelu, out);
}

// round 9
// speedup vs baseline: 2.3036x; 1.2676x over previous
#include <cuda_runtime.h>
#include <cuda_bf16.h>

#define Bb 128
#define Nn 1024
#define DMdim 64
#define K2 2048   // S * Nn

// Scratch (no allocs): static device globals
__device__ float g_gc[Bb * DMdim * Nn];                  // 32 MB
__device__ __nv_bfloat16 g_yhi[(size_t)8192 * 2048];     // 32 MB
__device__ __nv_bfloat16 g_ahi[2 * 1024 * 1024];         // 4 MB
__device__ float g_weff[128 * 68];
__device__ float g_beff[128];

// ---------------------------------------------------------------------------
__device__ __forceinline__ unsigned s2u(const void* p) {
    unsigned a;
    asm("{ .reg .u64 t; cvta.to.shared.u64 t, %1; cvt.u32.u64 %0, t; }"
        : "=r"(a) : "l"(p));
    return a;
}
#define CP16(dst, src) \
    asm volatile("cp.async.cg.shared.global [%0], [%1], 16;" :: "r"(dst), "l"(src))
#define CP_COMMIT() asm volatile("cp.async.commit_group;" ::: "memory")

// packed f32x2 helpers (FFMA2 path — B300 SASS, PTX-only)
__device__ __forceinline__ unsigned long long pack2(float a, float b) {
    unsigned long long r;
    asm("mov.b64 %0, {%1, %2};" : "=l"(r) : "f"(a), "f"(b));
    return r;
}
__device__ __forceinline__ unsigned long long bcast2(float a) {
    unsigned long long r;
    asm("mov.b64 %0, {%1, %1};" : "=l"(r) : "f"(a));
    return r;
}
__device__ __forceinline__ void ffma2(unsigned long long& d,
                                      unsigned long long a, unsigned long long b) {
    asm("fma.rn.f32x2 %0, %1, %2, %0;" : "+l"(d) : "l"(a), "l"(b));
}
__device__ __forceinline__ float2 unpack2(unsigned long long v) {
    float x, y;
    asm("mov.b64 {%0, %1}, %2;" : "=f"(x), "=f"(y) : "l"(v));
    return make_float2(x, y);
}

// ---------------------------------------------------------------------------
// adj -> bf16
// ---------------------------------------------------------------------------
__global__ __launch_bounds__(256) void k_adj(const float* __restrict__ adj)
{
    int i = blockIdx.x * 256 + threadIdx.x;   // 524288 float4s
    float4 v = ((const float4*)adj)[i];
    __nv_bfloat16 h0 = __float2bfloat16(v.x);
    __nv_bfloat16 h1 = __float2bfloat16(v.y);
    __nv_bfloat16 h2 = __float2bfloat16(v.z);
    __nv_bfloat16 h3 = __float2bfloat16(v.w);
    ((__nv_bfloat162*)g_ahi)[i * 2 + 0] = __halves2bfloat162(h0, h1);
    ((__nv_bfloat162*)g_ahi)[i * 2 + 1] = __halves2bfloat162(h2, h3);
}

// ---------------------------------------------------------------------------
// fold W_in into W_gc:  W_eff[o'][c'] (o' in [0,128), c' in [0,68))
// ---------------------------------------------------------------------------
__global__ __launch_bounds__(256) void k_weff(
    const float* __restrict__ W_in, const float* __restrict__ b_in,
    const float* __restrict__ W_gc)
{
    int tid = threadIdx.x;
    for (int i = tid; i < 128 * 68; i += 256) {
        int op = i / 68, cp = i - op * 68;
        const float* wg = W_gc + (op & 63) * 128 + (op >> 6) * 64;
        float s = 0.f;
        for (int c = 0; c < 64; c++) s = fmaf(wg[c], W_in[c * 68 + cp], s);
        g_weff[i] = s;
    }
    if (tid < 128) {
        const float* wg = W_gc + (tid & 63) * 128 + (tid >> 6) * 64;
        float s = 0.f;
        for (int c = 0; c < 64; c++) s = fmaf(wg[c], b_in[c], s);
        g_beff[tid] = s;
    }
}

// ---------------------------------------------------------------------------
// k_y: FFMA2, 4 cols/thread, 128 thr/block, 256 blocks. bf16-hi output only.
// ---------------------------------------------------------------------------
__global__ __launch_bounds__(128) void k_y(
    const float* __restrict__ x, const float* __restrict__ m,
    const float* __restrict__ u, const float* __restrict__ h)
{
    __shared__ unsigned long long WPs[68][64];   // weight pairs
    __shared__ unsigned long long bep[64];       // bias pairs
    for (int i = threadIdx.x; i < 68 * 64; i += 128) {
        int cp = i >> 6, p = i & 63;
        WPs[cp][p] = pack2(g_weff[(2 * p) * 68 + cp], g_weff[(2 * p + 1) * 68 + cp]);
    }
    if (threadIdx.x < 64)
        bep[threadIdx.x] = pack2(g_beff[2 * threadIdx.x], g_beff[2 * threadIdx.x + 1]);
    __syncthreads();

    int b = blockIdx.x >> 1;
    int n0 = (blockIdx.x & 1) * 512 + threadIdx.x * 4;

    for (int ch = 0; ch < 8; ch++) {
        int p0 = ch * 8;                         // pair base (16 outputs)
        unsigned long long acc[8][4];
#pragma unroll
        for (int i = 0; i < 8; i++) {
            unsigned long long bv = bep[p0 + i];
            acc[i][0] = bv; acc[i][1] = bv; acc[i][2] = bv; acc[i][3] = bv;
        }

#define YACC(cp, ptr) do {                                                     \
        float4 _v = *(const float4*)(ptr);                                     \
        unsigned long long _v0 = bcast2(_v.x), _v1 = bcast2(_v.y);             \
        unsigned long long _v2 = bcast2(_v.z), _v3 = bcast2(_v.w);             \
        _Pragma("unroll")                                                      \
        for (int i = 0; i < 8; i++) {                                          \
            unsigned long long _wp = WPs[cp][p0 + i];                          \
            ffma2(acc[i][0], _wp, _v0);                                        \
            ffma2(acc[i][1], _wp, _v1);                                        \
            ffma2(acc[i][2], _wp, _v2);                                        \
            ffma2(acc[i][3], _wp, _v3);                                        \
        }                                                                      \
    } while (0)

        YACC(0, &x[b * 1024 + n0]);
        YACC(1, &m[b * 1024 + n0]);
        YACC(2, &u[b * 2048 + n0]);
        YACC(3, &u[b * 2048 + 1024 + n0]);
        for (int c = 0; c < 64; c++)
            YACC(4 + c, &h[(b * 64 + c) * 1024 + n0]);
#undef YACC

#pragma unroll
        for (int i = 0; i < 8; i++) {
            float2 c0 = unpack2(acc[i][0]);  // (o=2i, n0) , (o=2i+1, n0)
            float2 c1 = unpack2(acc[i][1]);
            float2 c2 = unpack2(acc[i][2]);
            float2 c3 = unpack2(acc[i][3]);
#pragma unroll
            for (int q = 0; q < 2; q++) {
                int op = ch * 16 + 2 * i + q;
                float v0 = q ? c0.y : c0.x;
                float v1 = q ? c1.y : c1.x;
                float v2 = q ? c2.y : c2.x;
                float v3 = q ? c3.y : c3.x;
                int s = op >> 6, oc = op & 63;
                size_t yi = (size_t)(b * 64 + oc) * K2 + s * 1024 + n0;
                __nv_bfloat162 hp0 = __halves2bfloat162(
                    __float2bfloat16(v0), __float2bfloat16(v1));
                __nv_bfloat162 hp1 = __halves2bfloat162(
                    __float2bfloat16(v2), __float2bfloat16(v3));
                uint2 hw; hw.x = *(unsigned*)&hp0; hw.y = *(unsigned*)&hp1;
                *(uint2*)&g_yhi[yi] = hw;
            }
        }
    }
}

// ---------------------------------------------------------------------------
// GEMM: single-pass bf16 mma.sync   gc = yhi @ ahi (+ bias)
// BM=128 BN=128 BK=64, XOR-swizzled smem, 3-stage cp.async, 2 CTAs/SM.
// ---------------------------------------------------------------------------
#define BM 128
#define BN 128
#define BK 64
#define ASTG (128 * 128)
#define STGB (2 * ASTG)
#define GDYN (3 * STGB)
#define NCHK 32

__device__ __forceinline__ void ldsm4(unsigned* r, unsigned addr) {
    asm volatile("ldmatrix.sync.aligned.m8n8.x4.shared.b16 {%0,%1,%2,%3}, [%4];"
                 : "=r"(r[0]), "=r"(r[1]), "=r"(r[2]), "=r"(r[3]) : "r"(addr));
}
__device__ __forceinline__ void mma16816(float* c, const unsigned* a,
                                         unsigned b0, unsigned b1) {
    asm volatile(
        "mma.sync.aligned.m16n8k16.row.col.f32.bf16.bf16.f32 "
        "{%0,%1,%2,%3}, {%4,%5,%6,%7}, {%8,%9}, {%0,%1,%2,%3};"
        : "+f"(c[0]), "+f"(c[1]), "+f"(c[2]), "+f"(c[3])
        : "r"(a[0]), "r"(a[1]), "r"(a[2]), "r"(a[3]), "r"(b0), "r"(b1));
}

__device__ __forceinline__ void load_chunk(unsigned base, int st, int t,
                                           int bm, int bn, int tid)
{
    int k0 = t * BK;
    int s = k0 >> 10;
    int v0 = k0 & 1023;
    unsigned ab = base + st * STGB;
    unsigned bb = ab + ASTG;
#pragma unroll
    for (int i = 0; i < 4; i++) {
        int u2 = tid + i * 256;
        int row = u2 >> 3, j = u2 & 7;
        CP16(ab + row * 128 + ((j ^ (row & 7)) * 16),
             (const char*)(g_yhi + (size_t)(bm + row) * K2 + k0 + j * 8));
    }
#pragma unroll
    for (int i = 0; i < 4; i++) {
        int u2 = tid + i * 256;
        int row = u2 >> 3, j = u2 & 7;
        CP16(bb + row * 128 + ((j ^ (row & 7)) * 16),
             (const char*)(g_ahi + (size_t)s * 1048576 +
                           (size_t)(bn + row) * 1024 + v0 + j * 8));
    }
    CP_COMMIT();
}

__global__ __launch_bounds__(256, 2) void k_gemm_mma(const float* __restrict__ b_gc)
{
    extern __shared__ __align__(16) char dsm[];
    unsigned base = s2u(dsm);

    int tid = threadIdx.x;
    int lane = tid & 31;
    int wid = tid >> 5;
    int wm = wid >> 1;
    int wn = wid & 1;
    int bm = blockIdx.y * BM;
    int bn = blockIdx.x * BN;

    float acc[2][8][4];
#pragma unroll
    for (int i = 0; i < 2; i++)
#pragma unroll
        for (int j = 0; j < 8; j++)
#pragma unroll
            for (int q = 0; q < 4; q++) acc[i][j][q] = 0.f;

    load_chunk(base, 0, 0, bm, bn, tid);
    load_chunk(base, 1, 1, bm, bn, tid);

    int st = 0;
    for (int t = 0; t < NCHK; t++) {
        if (t == NCHK - 1) asm volatile("cp.async.wait_group 0;" ::: "memory");
        else               asm volatile("cp.async.wait_group 1;" ::: "memory");
        __syncthreads();

        if (t + 2 < NCHK) {
            int st2 = st + 2; if (st2 >= 3) st2 -= 3;
            load_chunk(base, st2, t + 2, bm, bn, tid);
        }

        unsigned abuf = base + st * STGB;
        unsigned bbuf = abuf + ASTG;

#pragma unroll
        for (int kk = 0; kk < 4; kk++) {
            unsigned ar[2][4];
#pragma unroll
            for (int mf = 0; mf < 2; mf++) {
                int mrow = wm * 32 + mf * 16 + (lane & 7) + ((lane >> 3) & 1) * 8;
                int uidx = kk * 2 + (lane >> 4);
                ldsm4(ar[mf], abuf + mrow * 128 + ((uidx ^ (mrow & 7)) * 16));
            }
            unsigned br[4][4];
#pragma unroll
            for (int nt = 0; nt < 4; nt++) {
                int nrow = wn * 64 + nt * 16 + (lane & 7) + (lane >> 4) * 8;
                int uidx = kk * 2 + ((lane >> 3) & 1);
                ldsm4(br[nt], bbuf + nrow * 128 + ((uidx ^ (nrow & 7)) * 16));
            }
#pragma unroll
            for (int mf = 0; mf < 2; mf++)
#pragma unroll
                for (int nt = 0; nt < 4; nt++) {
                    mma16816(acc[mf][nt * 2 + 0], ar[mf], br[nt][0], br[nt][1]);
                    mma16816(acc[mf][nt * 2 + 1], ar[mf], br[nt][2], br[nt][3]);
                }
        }
        st++; if (st >= 3) st = 0;
    }

#pragma unroll
    for (int mf = 0; mf < 2; mf++) {
        int r0 = bm + wm * 32 + mf * 16 + (lane >> 2);
        float bv0 = __ldg(&b_gc[r0 & 63]);
        float bv1 = __ldg(&b_gc[(r0 + 8) & 63]);
#pragma unroll
        for (int nf = 0; nf < 8; nf++) {
            int col = bn + wn * 64 + nf * 8 + (lane & 3) * 2;
            float* c4 = acc[mf][nf];
            *(float2*)&g_gc[(size_t)r0 * 1024 + col] =
                make_float2(c4[0] + bv0, c4[1] + bv0);
            *(float2*)&g_gc[(size_t)(r0 + 8) * 1024 + col] =
                make_float2(c4[2] + bv1, c4[3] + bv1);
        }
    }
}

// ---------------------------------------------------------------------------
// k_out: FFMA2, 4 cols/thread, 128 thr/block, 256 blocks.
// ---------------------------------------------------------------------------
__global__ __launch_bounds__(128) void k_out(
    const float* __restrict__ h, const float* __restrict__ W_out,
    const float* __restrict__ b_out, const float* __restrict__ W_read,
    const float* __restrict__ b_read, const float* __restrict__ prelu_w,
    float* __restrict__ out)
{
    __shared__ unsigned long long WoPs[128][32];
    __shared__ unsigned long long bop[32];
    __shared__ float Wr[128];
    for (int i = threadIdx.x; i < 128 * 32; i += 128) {
        int c = i >> 5, p = i & 31;
        WoPs[c][p] = pack2(W_out[(2 * p) * 128 + c], W_out[(2 * p + 1) * 128 + c]);
    }
    Wr[threadIdx.x] = W_read[threadIdx.x];
    if (threadIdx.x < 32)
        bop[threadIdx.x] = pack2(b_out[2 * threadIdx.x], b_out[2 * threadIdx.x + 1]);
    __syncthreads();

    int b = blockIdx.x >> 1;
    int n0 = (blockIdx.x & 1) * 512 + threadIdx.x * 4;
    float pw = __ldg(prelu_w);
    float brd = __ldg(b_read);
    float racc[4] = {brd, brd, brd, brd};
    float* out2 = out + (size_t)Bb * Nn;

    for (int ch = 0; ch < 4; ch++) {
        int p0 = ch * 8;                          // 16 outputs = 8 pairs
        unsigned long long acc[8][4];
#pragma unroll
        for (int i = 0; i < 8; i++) {
            unsigned long long bv = bop[p0 + i];
            acc[i][0] = bv; acc[i][1] = bv; acc[i][2] = bv; acc[i][3] = bv;
        }

        for (int c = 0; c < 64; c++) {
            float4 g = *(const float4*)&g_gc[(size_t)(b * 64 + c) * 1024 + n0];
            unsigned long long v0 = bcast2(g.x), v1 = bcast2(g.y);
            unsigned long long v2 = bcast2(g.z), v3 = bcast2(g.w);
#pragma unroll
            for (int i = 0; i < 8; i++) {
                unsigned long long wp = WoPs[c][p0 + i];
                ffma2(acc[i][0], wp, v0);
                ffma2(acc[i][1], wp, v1);
                ffma2(acc[i][2], wp, v2);
                ffma2(acc[i][3], wp, v3);
            }
        }
        for (int c = 0; c < 64; c++) {
            float4 hv = *(const float4*)&h[(size_t)(b * 64 + c) * 1024 + n0];
            unsigned long long v0 = bcast2(hv.x), v1 = bcast2(hv.y);
            unsigned long long v2 = bcast2(hv.z), v3 = bcast2(hv.w);
#pragma unroll
            for (int i = 0; i < 8; i++) {
                unsigned long long wp = WoPs[64 + c][p0 + i];
                ffma2(acc[i][0], wp, v0);
                ffma2(acc[i][1], wp, v1);
                ffma2(acc[i][2], wp, v2);
                ffma2(acc[i][3], wp, v3);
            }
        }

#pragma unroll
        for (int i = 0; i < 8; i++) {
            float2 c0 = unpack2(acc[i][0]);
            float2 c1 = unpack2(acc[i][1]);
            float2 c2 = unpack2(acc[i][2]);
            float2 c3 = unpack2(acc[i][3]);
#pragma unroll
            for (int q = 0; q < 2; q++) {
                int o = ch * 16 + 2 * i + q;
                float v0 = q ? c0.y : c0.x;
                float v1 = q ? c1.y : c1.x;
                float v2 = q ? c2.y : c2.x;
                float v3 = q ? c3.y : c3.x;
                float4 p;
                p.x = v0 >= 0.f ? v0 : pw * v0;
                p.y = v1 >= 0.f ? v1 : pw * v1;
                p.z = v2 >= 0.f ? v2 : pw * v2;
                p.w = v3 >= 0.f ? v3 : pw * v3;
                *(float4*)&out2[(size_t)(b * 128 + o) * 1024 + n0] = p;
                float wr = Wr[o];
                racc[0] = fmaf(wr, p.x, racc[0]);
                racc[1] = fmaf(wr, p.y, racc[1]);
                racc[2] = fmaf(wr, p.z, racc[2]);
                racc[3] = fmaf(wr, p.w, racc[3]);
            }
        }
    }

    for (int c = 0; c < 64; c++) {
        float4 hv = *(const float4*)&h[(size_t)(b * 64 + c) * 1024 + n0];
        *(float4*)&out2[(size_t)(b * 128 + 64 + c) * 1024 + n0] = hv;
        float wr = Wr[64 + c];
        racc[0] = fmaf(wr, hv.x, racc[0]);
        racc[1] = fmaf(wr, hv.y, racc[1]);
        racc[2] = fmaf(wr, hv.z, racc[2]);
        racc[3] = fmaf(wr, hv.w, racc[3]);
    }
    *(float4*)&out[(size_t)b * 1024 + n0] =
        make_float4(racc[0], racc[1], racc[2], racc[3]);
}

// ---------------------------------------------------------------------------
extern "C" void kernel_launch(void* const* d_in, const int* in_sizes, int n_in,
                              void* d_out, int out_size)
{
    const float* x      = (const float*)d_in[0];
    const float* m      = (const float*)d_in[1];
    const float* u      = (const float*)d_in[2];
    const float* h      = (const float*)d_in[3];
    const float* adj    = (const float*)d_in[4];
    const float* W_in   = (const float*)d_in[5];
    const float* b_in   = (const float*)d_in[6];
    const float* W_gc   = (const float*)d_in[7];
    const float* b_gc   = (const float*)d_in[8];
    const float* W_out  = (const float*)d_in[9];
    const float* b_out  = (const float*)d_in[10];
    const float* W_read = (const float*)d_in[11];
    const float* b_read = (const float*)d_in[12];
    const float* prelu  = (const float*)d_in[13];
    float* out = (float*)d_out;

    cudaFuncSetAttribute(k_gemm_mma, cudaFuncAttributeMaxDynamicSharedMemorySize, GDYN);

    k_adj<<<2048, 256>>>(adj);
    k_weff<<<1, 256>>>(W_in, b_in, W_gc);
    k_y<<<256, 128>>>(x, m, u, h);
    dim3 g(Nn / BN, (Bb * DMdim) / BM);   // (8, 64) = 512 CTAs
    k_gemm_mma<<<g, 256, GDYN>>>(b_gc);
    k_out<<<256, 128>>>(h, W_out, b_out, W_read, b_read, prelu, out);
}

// round 10
// speedup vs baseline: 2.4644x; 1.0698x over previous
#include <cuda_runtime.h>
#include <cuda_bf16.h>

#define Bb 128
#define Nn 1024
#define DMdim 64
#define K2 2048   // S * Nn

// Scratch (no allocs): static device globals
__device__ float g_gc[Bb * DMdim * Nn];                  // 32 MB
__device__ __nv_bfloat16 g_yhi[(size_t)8192 * 2048];     // 32 MB
__device__ __nv_bfloat16 g_ahi[2 * 1024 * 1024];         // 4 MB
__device__ float g_weff[128 * 68];
__device__ float g_beff[128];

// ---------------------------------------------------------------------------
__device__ __forceinline__ unsigned s2u(const void* p) {
    unsigned a;
    asm("{ .reg .u64 t; cvta.to.shared.u64 t, %1; cvt.u32.u64 %0, t; }"
        : "=r"(a) : "l"(p));
    return a;
}
#define CP16(dst, src) \
    asm volatile("cp.async.cg.shared.global [%0], [%1], 16;" :: "r"(dst), "l"(src))
#define CP_COMMIT() asm volatile("cp.async.commit_group;" ::: "memory")
#define STS16(addr, v) \
    asm volatile("st.shared.u16 [%0], %1;" :: "r"(addr), "h"(v))

__device__ __forceinline__ unsigned short bf16u(float f) {
    __nv_bfloat16 t = __float2bfloat16(f);
    return *(unsigned short*)&t;
}

// packed f32x2 helpers (FFMA2 path — B300 SASS, PTX-only)
__device__ __forceinline__ unsigned long long pack2(float a, float b) {
    unsigned long long r;
    asm("mov.b64 %0, {%1, %2};" : "=l"(r) : "f"(a), "f"(b));
    return r;
}
__device__ __forceinline__ unsigned long long bcast2(float a) {
    unsigned long long r;
    asm("mov.b64 %0, {%1, %1};" : "=l"(r) : "f"(a));
    return r;
}
__device__ __forceinline__ void ffma2(unsigned long long& d,
                                      unsigned long long a, unsigned long long b) {
    asm("fma.rn.f32x2 %0, %1, %2, %0;" : "+l"(d) : "l"(a), "l"(b));
}
__device__ __forceinline__ float2 unpack2(unsigned long long v) {
    float x, y;
    asm("mov.b64 {%0, %1}, %2;" : "=f"(x), "=f"(y) : "l"(v));
    return make_float2(x, y);
}

__device__ __forceinline__ void ldsm4(unsigned* r, unsigned addr) {
    asm volatile("ldmatrix.sync.aligned.m8n8.x4.shared.b16 {%0,%1,%2,%3}, [%4];"
                 : "=r"(r[0]), "=r"(r[1]), "=r"(r[2]), "=r"(r[3]) : "r"(addr));
}
__device__ __forceinline__ void mma16816(float* c, const unsigned* a,
                                         unsigned b0, unsigned b1) {
    asm volatile(
        "mma.sync.aligned.m16n8k16.row.col.f32.bf16.bf16.f32 "
        "{%0,%1,%2,%3}, {%4,%5,%6,%7}, {%8,%9}, {%0,%1,%2,%3};"
        : "+f"(c[0]), "+f"(c[1]), "+f"(c[2]), "+f"(c[3])
        : "r"(a[0]), "r"(a[1]), "r"(a[2]), "r"(a[3]), "r"(b0), "r"(b1));
}

// ---------------------------------------------------------------------------
// adj -> bf16
// ---------------------------------------------------------------------------
__global__ __launch_bounds__(256) void k_adj(const float* __restrict__ adj)
{
    int i = blockIdx.x * 256 + threadIdx.x;   // 524288 float4s
    float4 v = ((const float4*)adj)[i];
    ((__nv_bfloat162*)g_ahi)[i * 2 + 0] = __halves2bfloat162(
        __float2bfloat16(v.x), __float2bfloat16(v.y));
    ((__nv_bfloat162*)g_ahi)[i * 2 + 1] = __halves2bfloat162(
        __float2bfloat16(v.z), __float2bfloat16(v.w));
}

// ---------------------------------------------------------------------------
// fold W_in into W_gc:  W_eff[o'][c'] (o' in [0,128), c' in [0,68))
// ---------------------------------------------------------------------------
__global__ __launch_bounds__(256) void k_weff(
    const float* __restrict__ W_in, const float* __restrict__ b_in,
    const float* __restrict__ W_gc)
{
    int tid = threadIdx.x;
    for (int i = tid; i < 128 * 68; i += 256) {
        int op = i / 68, cp = i - op * 68;
        const float* wg = W_gc + (op & 63) * 128 + (op >> 6) * 64;
        float s = 0.f;
        for (int c = 0; c < 64; c++) s = fmaf(wg[c], W_in[c * 68 + cp], s);
        g_weff[i] = s;
    }
    if (tid < 128) {
        const float* wg = W_gc + (tid & 63) * 128 + (tid >> 6) * 64;
        float s = 0.f;
        for (int c = 0; c < 64; c++) s = fmaf(wg[c], b_in[c], s);
        g_beff[tid] = s;
    }
}

// ---------------------------------------------------------------------------
// k_y: FFMA2, 4 cols/thread, 128 thr/block, 256 blocks. bf16-hi output only.
// ---------------------------------------------------------------------------
__global__ __launch_bounds__(128) void k_y(
    const float* __restrict__ x, const float* __restrict__ m,
    const float* __restrict__ u, const float* __restrict__ h)
{
    __shared__ unsigned long long WPs[68][64];   // weight pairs
    __shared__ unsigned long long bep[64];       // bias pairs
    for (int i = threadIdx.x; i < 68 * 64; i += 128) {
        int cp = i >> 6, p = i & 63;
        WPs[cp][p] = pack2(g_weff[(2 * p) * 68 + cp], g_weff[(2 * p + 1) * 68 + cp]);
    }
    if (threadIdx.x < 64)
        bep[threadIdx.x] = pack2(g_beff[2 * threadIdx.x], g_beff[2 * threadIdx.x + 1]);
    __syncthreads();

    int b = blockIdx.x >> 1;
    int n0 = (blockIdx.x & 1) * 512 + threadIdx.x * 4;

    for (int ch = 0; ch < 8; ch++) {
        int p0 = ch * 8;                         // pair base (16 outputs)
        unsigned long long acc[8][4];
#pragma unroll
        for (int i = 0; i < 8; i++) {
            unsigned long long bv = bep[p0 + i];
            acc[i][0] = bv; acc[i][1] = bv; acc[i][2] = bv; acc[i][3] = bv;
        }

#define YACC(cp, ptr) do {                                                     \
        float4 _v = *(const float4*)(ptr);                                     \
        unsigned long long _v0 = bcast2(_v.x), _v1 = bcast2(_v.y);             \
        unsigned long long _v2 = bcast2(_v.z), _v3 = bcast2(_v.w);             \
        _Pragma("unroll")                                                      \
        for (int i = 0; i < 8; i++) {                                          \
            unsigned long long _wp = WPs[cp][p0 + i];                          \
            ffma2(acc[i][0], _wp, _v0);                                        \
            ffma2(acc[i][1], _wp, _v1);                                        \
            ffma2(acc[i][2], _wp, _v2);                                        \
            ffma2(acc[i][3], _wp, _v3);                                        \
        }                                                                      \
    } while (0)

        YACC(0, &x[b * 1024 + n0]);
        YACC(1, &m[b * 1024 + n0]);
        YACC(2, &u[b * 2048 + n0]);
        YACC(3, &u[b * 2048 + 1024 + n0]);
        for (int c = 0; c < 64; c++)
            YACC(4 + c, &h[(b * 64 + c) * 1024 + n0]);
#undef YACC

#pragma unroll
        for (int i = 0; i < 8; i++) {
            float2 c0 = unpack2(acc[i][0]);
            float2 c1 = unpack2(acc[i][1]);
            float2 c2 = unpack2(acc[i][2]);
            float2 c3 = unpack2(acc[i][3]);
#pragma unroll
            for (int q = 0; q < 2; q++) {
                int op = ch * 16 + 2 * i + q;
                float v0 = q ? c0.y : c0.x;
                float v1 = q ? c1.y : c1.x;
                float v2 = q ? c2.y : c2.x;
                float v3 = q ? c3.y : c3.x;
                int s = op >> 6, oc = op & 63;
                size_t yi = (size_t)(b * 64 + oc) * K2 + s * 1024 + n0;
                __nv_bfloat162 hp0 = __halves2bfloat162(
                    __float2bfloat16(v0), __float2bfloat16(v1));
                __nv_bfloat162 hp1 = __halves2bfloat162(
                    __float2bfloat16(v2), __float2bfloat16(v3));
                uint2 hw; hw.x = *(unsigned*)&hp0; hw.y = *(unsigned*)&hp1;
                *(uint2*)&g_yhi[yi] = hw;
            }
        }
    }
}

// ---------------------------------------------------------------------------
// GEMM: single-pass bf16 mma.sync   gc = yhi @ ahi (+ bias)   [proven]
// ---------------------------------------------------------------------------
#define BM 128
#define BN 128
#define BK 64
#define ASTG (128 * 128)
#define STGB (2 * ASTG)
#define GDYN (3 * STGB)
#define NCHK 32

__device__ __forceinline__ void load_chunk(unsigned base, int st, int t,
                                           int bm, int bn, int tid)
{
    int k0 = t * BK;
    int s = k0 >> 10;
    int v0 = k0 & 1023;
    unsigned ab = base + st * STGB;
    unsigned bb = ab + ASTG;
#pragma unroll
    for (int i = 0; i < 4; i++) {
        int u2 = tid + i * 256;
        int row = u2 >> 3, j = u2 & 7;
        CP16(ab + row * 128 + ((j ^ (row & 7)) * 16),
             (const char*)(g_yhi + (size_t)(bm + row) * K2 + k0 + j * 8));
    }
#pragma unroll
    for (int i = 0; i < 4; i++) {
        int u2 = tid + i * 256;
        int row = u2 >> 3, j = u2 & 7;
        CP16(bb + row * 128 + ((j ^ (row & 7)) * 16),
             (const char*)(g_ahi + (size_t)s * 1048576 +
                           (size_t)(bn + row) * 1024 + v0 + j * 8));
    }
    CP_COMMIT();
}

__global__ __launch_bounds__(256, 2) void k_gemm_mma(const float* __restrict__ b_gc)
{
    extern __shared__ __align__(16) char dsm[];
    unsigned base = s2u(dsm);

    int tid = threadIdx.x;
    int lane = tid & 31;
    int wid = tid >> 5;
    int wm = wid >> 1;
    int wn = wid & 1;
    int bm = blockIdx.y * BM;
    int bn = blockIdx.x * BN;

    float acc[2][8][4];
#pragma unroll
    for (int i = 0; i < 2; i++)
#pragma unroll
        for (int j = 0; j < 8; j++)
#pragma unroll
            for (int q = 0; q < 4; q++) acc[i][j][q] = 0.f;

    load_chunk(base, 0, 0, bm, bn, tid);
    load_chunk(base, 1, 1, bm, bn, tid);

    int st = 0;
    for (int t = 0; t < NCHK; t++) {
        if (t == NCHK - 1) asm volatile("cp.async.wait_group 0;" ::: "memory");
        else               asm volatile("cp.async.wait_group 1;" ::: "memory");
        __syncthreads();

        if (t + 2 < NCHK) {
            int st2 = st + 2; if (st2 >= 3) st2 -= 3;
            load_chunk(base, st2, t + 2, bm, bn, tid);
        }

        unsigned abuf = base + st * STGB;
        unsigned bbuf = abuf + ASTG;

#pragma unroll
        for (int kk = 0; kk < 4; kk++) {
            unsigned ar[2][4];
#pragma unroll
            for (int mf = 0; mf < 2; mf++) {
                int mrow = wm * 32 + mf * 16 + (lane & 7) + ((lane >> 3) & 1) * 8;
                int uidx = kk * 2 + (lane >> 4);
                ldsm4(ar[mf], abuf + mrow * 128 + ((uidx ^ (mrow & 7)) * 16));
            }
            unsigned br[4][4];
#pragma unroll
            for (int nt = 0; nt < 4; nt++) {
                int nrow = wn * 64 + nt * 16 + (lane & 7) + (lane >> 4) * 8;
                int uidx = kk * 2 + ((lane >> 3) & 1);
                ldsm4(br[nt], bbuf + nrow * 128 + ((uidx ^ (nrow & 7)) * 16));
            }
#pragma unroll
            for (int mf = 0; mf < 2; mf++)
#pragma unroll
                for (int nt = 0; nt < 4; nt++) {
                    mma16816(acc[mf][nt * 2 + 0], ar[mf], br[nt][0], br[nt][1]);
                    mma16816(acc[mf][nt * 2 + 1], ar[mf], br[nt][2], br[nt][3]);
                }
        }
        st++; if (st >= 3) st = 0;
    }

#pragma unroll
    for (int mf = 0; mf < 2; mf++) {
        int r0 = bm + wm * 32 + mf * 16 + (lane >> 2);
        float bv0 = __ldg(&b_gc[r0 & 63]);
        float bv1 = __ldg(&b_gc[(r0 + 8) & 63]);
#pragma unroll
        for (int nf = 0; nf < 8; nf++) {
            int col = bn + wn * 64 + nf * 8 + (lane & 3) * 2;
            float* c4 = acc[mf][nf];
            *(float2*)&g_gc[(size_t)r0 * 1024 + col] =
                make_float2(c4[0] + bv0, c4[1] + bv0);
            *(float2*)&g_gc[(size_t)(r0 + 8) * 1024 + col] =
                make_float2(c4[2] + bv1, c4[3] + bv1);
        }
    }
}

// ---------------------------------------------------------------------------
// k_out_mma: tensor-core epilogue. Per CTA: 128 output columns of one b.
//   out_pre[o][n] = b_out[o] + W[o,:]·[gc; h]  via M=64,N=128,K=256 mma:
//   K blocks: [0,64) Wgc_hi·gc_hi | [64,128) Wh_hi·h_hi
//             [128,192) Wh_hi·h_lo | [192,256) Wh_lo·h_hi
//   Then PReLU -> out2 + smem; readout conv + exact h copy.
// smem: A 64x512B = 32KB, B 128x512B = 64KB (prelu_s reuses, stride 132 fl).
// ---------------------------------------------------------------------------
#define ODYN 98304

__global__ __launch_bounds__(256, 2) void k_out_mma(
    const float* __restrict__ h, const float* __restrict__ W_out,
    const float* __restrict__ b_out, const float* __restrict__ W_read,
    const float* __restrict__ b_read, const float* __restrict__ prelu_w,
    float* __restrict__ out)
{
    extern __shared__ __align__(16) char dsm[];
    unsigned As = s2u(dsm);
    unsigned Bs = As + 32768;
    float* prelu_s = (float*)dsm;               // reused after mma (132 stride)

    __shared__ float Wr_s[128];
    __shared__ float bo_s[64];

    int tid = threadIdx.x;
    int lane = tid & 31;
    int wid = tid >> 5;
    int b = blockIdx.x >> 3;
    int n0 = (blockIdx.x & 7) * 128;

    if (tid < 128) Wr_s[tid] = W_read[tid];
    if (tid >= 128 && tid < 192) bo_s[tid - 128] = b_out[tid - 128];

    // ---- stage B: gc (k 0..63) ----
#pragma unroll
    for (int i = 0; i < 8; i++) {
        int u = tid + i * 256;
        int c = u >> 5, f4 = u & 31;
        float4 g = *(const float4*)&g_gc[(size_t)(b * 64 + c) * 1024 + n0 + f4 * 4];
        float vv[4] = {g.x, g.y, g.z, g.w};
#pragma unroll
        for (int j = 0; j < 4; j++) {
            int n = f4 * 4 + j;
            STS16(Bs + n * 512 + (((c >> 3) ^ (n & 7)) * 16) + (c & 7) * 2,
                  bf16u(vv[j]));
        }
    }
    // ---- stage B: h hi (k 64.. & 192..), lo (k 128..) ----
#pragma unroll
    for (int i = 0; i < 8; i++) {
        int u = tid + i * 256;
        int c = u >> 5, f4 = u & 31;
        float4 hv = *(const float4*)&h[(size_t)(b * 64 + c) * 1024 + n0 + f4 * 4];
        float vv[4] = {hv.x, hv.y, hv.z, hv.w};
#pragma unroll
        for (int j = 0; j < 4; j++) {
            int n = f4 * 4 + j;
            __nv_bfloat16 hb = __float2bfloat16(vv[j]);
            unsigned short hu = *(unsigned short*)&hb;
            unsigned short lu = bf16u(vv[j] - __bfloat162float(hb));
            unsigned rowb = Bs + n * 512;
            unsigned x7 = (n & 7);
            STS16(rowb + (((8  + (c >> 3)) ^ x7) * 16) + (c & 7) * 2, hu);
            STS16(rowb + (((24 + (c >> 3)) ^ x7) * 16) + (c & 7) * 2, hu);
            STS16(rowb + (((16 + (c >> 3)) ^ x7) * 16) + (c & 7) * 2, lu);
        }
    }
    // ---- stage A: W_out [64 o x 128 c] ----
#pragma unroll
    for (int i = 0; i < 8; i++) {
        int u = tid + i * 256;
        int o = u >> 5, f4 = u & 31;
        float4 w = *(const float4*)&W_out[o * 128 + f4 * 4];
        float vv[4] = {w.x, w.y, w.z, w.w};
        unsigned rowa = As + o * 512;
        unsigned x7 = (o & 7);
#pragma unroll
        for (int j = 0; j < 4; j++) {
            int c = f4 * 4 + j;
            if (c < 64) {
                STS16(rowa + (((c >> 3) ^ x7) * 16) + (c & 7) * 2, bf16u(vv[j]));
            } else {
                __nv_bfloat16 hb = __float2bfloat16(vv[j]);
                unsigned short hu = *(unsigned short*)&hb;
                unsigned short lu = bf16u(vv[j] - __bfloat162float(hb));
                int k1 = c;          // 64..127  (hi)
                int k2 = c + 64;     // 128..191 (hi)
                int k3 = c + 128;    // 192..255 (lo)
                STS16(rowa + (((k1 >> 3) ^ x7) * 16) + (k1 & 7) * 2, hu);
                STS16(rowa + (((k2 >> 3) ^ x7) * 16) + (k2 & 7) * 2, hu);
                STS16(rowa + (((k3 >> 3) ^ x7) * 16) + (k3 & 7) * 2, lu);
            }
        }
    }
    __syncthreads();

    // ---- mma: M=64 N=128 K=256; 8 warps, warp tile m16 x n64 ----
    int wm = wid >> 1;   // 0..3
    int wn = wid & 1;    // 0..1
    float acc[8][4];
#pragma unroll
    for (int j = 0; j < 8; j++)
#pragma unroll
        for (int q = 0; q < 4; q++) acc[j][q] = 0.f;

#pragma unroll
    for (int kk = 0; kk < 16; kk++) {
        unsigned ar[4];
        int mrow = wm * 16 + (lane & 7) + ((lane >> 3) & 1) * 8;
        int uA = kk * 2 + (lane >> 4);
        ldsm4(ar, As + mrow * 512 + ((uA ^ (mrow & 7)) * 16));
        unsigned br[4][4];
#pragma unroll
        for (int nt = 0; nt < 4; nt++) {
            int nrow = wn * 64 + nt * 16 + (lane & 7) + (lane >> 4) * 8;
            int uB = kk * 2 + ((lane >> 3) & 1);
            ldsm4(br[nt], Bs + nrow * 512 + ((uB ^ (nrow & 7)) * 16));
        }
#pragma unroll
        for (int nt = 0; nt < 4; nt++) {
            mma16816(acc[nt * 2 + 0], ar, br[nt][0], br[nt][1]);
            mma16816(acc[nt * 2 + 1], ar, br[nt][2], br[nt][3]);
        }
    }
    __syncthreads();   // smem reads done; safe to overwrite with prelu_s

    // ---- epilogue: bias + PReLU -> out2 + prelu_s ----
    float pw = __ldg(prelu_w);
    float* out2 = out + (size_t)Bb * Nn;
    int o0 = wm * 16 + (lane >> 2);
    float b0v = bo_s[o0];
    float b1v = bo_s[o0 + 8];
#pragma unroll
    for (int nt = 0; nt < 4; nt++)
#pragma unroll
        for (int q = 0; q < 2; q++) {
            int ncol = wn * 64 + nt * 16 + q * 8 + (lane & 3) * 2;
            float* c4 = acc[nt * 2 + q];
            float v0 = c4[0] + b0v, v1 = c4[1] + b0v;
            float v2 = c4[2] + b1v, v3 = c4[3] + b1v;
            float p0 = v0 >= 0.f ? v0 : pw * v0;
            float p1 = v1 >= 0.f ? v1 : pw * v1;
            float p2 = v2 >= 0.f ? v2 : pw * v2;
            float p3 = v3 >= 0.f ? v3 : pw * v3;
            *(float2*)&out2[(size_t)(b * 128 + o0) * 1024 + n0 + ncol] =
                make_float2(p0, p1);
            *(float2*)&out2[(size_t)(b * 128 + o0 + 8) * 1024 + n0 + ncol] =
                make_float2(p2, p3);
            *(float2*)&prelu_s[o0 * 132 + ncol] = make_float2(p0, p1);
            *(float2*)&prelu_s[(o0 + 8) * 132 + ncol] = make_float2(p2, p3);
        }
    __syncthreads();

    // ---- readout conv (tid<128) + exact h copy (tid>=128) ----
    if (tid < 128) {
        int n = tid;
        float racc = __ldg(b_read);
        for (int o = 0; o < 64; o++)
            racc = fmaf(Wr_s[o], prelu_s[o * 132 + n], racc);
        for (int c = 0; c < 64; c++)
            racc = fmaf(Wr_s[64 + c],
                        h[(size_t)(b * 64 + c) * 1024 + n0 + n], racc);
        out[(size_t)b * 1024 + n0 + n] = racc;
    } else {
        int t2 = tid - 128;
#pragma unroll
        for (int i = 0; i < 16; i++) {
            int u = t2 + i * 128;
            int c = u >> 5, f4 = u & 31;
            float4 hv = *(const float4*)&h[(size_t)(b * 64 + c) * 1024 + n0 + f4 * 4];
            *(float4*)&out2[(size_t)(b * 128 + 64 + c) * 1024 + n0 + f4 * 4] = hv;
        }
    }
}

// ---------------------------------------------------------------------------
extern "C" void kernel_launch(void* const* d_in, const int* in_sizes, int n_in,
                              void* d_out, int out_size)
{
    const float* x      = (const float*)d_in[0];
    const float* m      = (const float*)d_in[1];
    const float* u      = (const float*)d_in[2];
    const float* h      = (const float*)d_in[3];
    const float* adj    = (const float*)d_in[4];
    const float* W_in   = (const float*)d_in[5];
    const float* b_in   = (const float*)d_in[6];
    const float* W_gc   = (const float*)d_in[7];
    const float* b_gc   = (const float*)d_in[8];
    const float* W_out  = (const float*)d_in[9];
    const float* b_out  = (const float*)d_in[10];
    const float* W_read = (const float*)d_in[11];
    const float* b_read = (const float*)d_in[12];
    const float* prelu  = (const float*)d_in[13];
    float* out = (float*)d_out;

    cudaFuncSetAttribute(k_gemm_mma, cudaFuncAttributeMaxDynamicSharedMemorySize, GDYN);
    cudaFuncSetAttribute(k_out_mma, cudaFuncAttributeMaxDynamicSharedMemorySize, ODYN);

    k_adj<<<2048, 256>>>(adj);
    k_weff<<<1, 256>>>(W_in, b_in, W_gc);
    k_y<<<256, 128>>>(x, m, u, h);
    dim3 g(Nn / BN, (Bb * DMdim) / BM);   // (8, 64) = 512 CTAs
    k_gemm_mma<<<g, 256, GDYN>>>(b_gc);
    k_out_mma<<<1024, 256, ODYN>>>(h, W_out, b_out, W_read, b_read, prelu, out);
}

// round 11
// speedup vs baseline: 2.8804x; 1.1688x over previous
#include <cuda_runtime.h>
#include <cuda_bf16.h>

#define Bb 128
#define Nn 1024
#define DMdim 64
#define K2 2048   // S * Nn

// Scratch (no allocs): static device globals
__device__ float g_gc[Bb * DMdim * Nn];                  // 32 MB
__device__ __nv_bfloat16 g_yhi[(size_t)8192 * 2048];     // 32 MB
__device__ __nv_bfloat16 g_ahi[2 * 1024 * 1024];         // 4 MB
__device__ float g_weff[128 * 68];
__device__ float g_beff[128];

// ---------------------------------------------------------------------------
__device__ __forceinline__ unsigned s2u(const void* p) {
    unsigned a;
    asm("{ .reg .u64 t; cvta.to.shared.u64 t, %1; cvt.u32.u64 %0, t; }"
        : "=r"(a) : "l"(p));
    return a;
}
#define CP16(dst, src) \
    asm volatile("cp.async.cg.shared.global [%0], [%1], 16;" :: "r"(dst), "l"(src))
#define CP_COMMIT() asm volatile("cp.async.commit_group;" ::: "memory")
#define STS16(addr, v) \
    asm volatile("st.shared.u16 [%0], %1;" :: "r"(addr), "h"(v))

__device__ __forceinline__ unsigned short bf16u(float f) {
    __nv_bfloat16 t = __float2bfloat16(f);
    return *(unsigned short*)&t;
}

// packed f32x2 helpers (FFMA2 path — B300 SASS, PTX-only)
__device__ __forceinline__ unsigned long long pack2(float a, float b) {
    unsigned long long r;
    asm("mov.b64 %0, {%1, %2};" : "=l"(r) : "f"(a), "f"(b));
    return r;
}
__device__ __forceinline__ unsigned long long bcast2(float a) {
    unsigned long long r;
    asm("mov.b64 %0, {%1, %1};" : "=l"(r) : "f"(a));
    return r;
}
__device__ __forceinline__ void ffma2(unsigned long long& d,
                                      unsigned long long a, unsigned long long b) {
    asm("fma.rn.f32x2 %0, %1, %2, %0;" : "+l"(d) : "l"(a), "l"(b));
}
__device__ __forceinline__ float2 unpack2(unsigned long long v) {
    float x, y;
    asm("mov.b64 {%0, %1}, %2;" : "=f"(x), "=f"(y) : "l"(v));
    return make_float2(x, y);
}

__device__ __forceinline__ void ldsm4(unsigned* r, unsigned addr) {
    asm volatile("ldmatrix.sync.aligned.m8n8.x4.shared.b16 {%0,%1,%2,%3}, [%4];"
                 : "=r"(r[0]), "=r"(r[1]), "=r"(r[2]), "=r"(r[3]) : "r"(addr));
}
__device__ __forceinline__ void mma16816(float* c, const unsigned* a,
                                         unsigned b0, unsigned b1) {
    asm volatile(
        "mma.sync.aligned.m16n8k16.row.col.f32.bf16.bf16.f32 "
        "{%0,%1,%2,%3}, {%4,%5,%6,%7}, {%8,%9}, {%0,%1,%2,%3};"
        : "+f"(c[0]), "+f"(c[1]), "+f"(c[2]), "+f"(c[3])
        : "r"(a[0]), "r"(a[1]), "r"(a[2]), "r"(a[3]), "r"(b0), "r"(b1));
}

// ---------------------------------------------------------------------------
// adj -> bf16
// ---------------------------------------------------------------------------
__global__ __launch_bounds__(256) void k_adj(const float* __restrict__ adj)
{
    int i = blockIdx.x * 256 + threadIdx.x;   // 524288 float4s
    float4 v = ((const float4*)adj)[i];
    ((__nv_bfloat162*)g_ahi)[i * 2 + 0] = __halves2bfloat162(
        __float2bfloat16(v.x), __float2bfloat16(v.y));
    ((__nv_bfloat162*)g_ahi)[i * 2 + 1] = __halves2bfloat162(
        __float2bfloat16(v.z), __float2bfloat16(v.w));
}

// ---------------------------------------------------------------------------
// fold W_in into W_gc — parallel over 35 blocks (one dot per thread)
// ---------------------------------------------------------------------------
__global__ __launch_bounds__(256) void k_weff(
    const float* __restrict__ W_in, const float* __restrict__ b_in,
    const float* __restrict__ W_gc)
{
    int i = blockIdx.x * 256 + threadIdx.x;
    if (blockIdx.x < 34) {                      // 34*256 = 8704 weights
        int op = i / 68, cp = i - op * 68;
        const float* wg = W_gc + (op & 63) * 128 + (op >> 6) * 64;
        float s = 0.f;
#pragma unroll 8
        for (int c = 0; c < 64; c++) s = fmaf(wg[c], W_in[c * 68 + cp], s);
        g_weff[op * 68 + cp] = s;
    } else if (threadIdx.x < 128) {
        int op = threadIdx.x;
        const float* wg = W_gc + (op & 63) * 128 + (op >> 6) * 64;
        float s = 0.f;
#pragma unroll 8
        for (int c = 0; c < 64; c++) s = fmaf(wg[c], b_in[c], s);
        g_beff[op] = s;
    }
}

// ---------------------------------------------------------------------------
// k_y: FFMA2, 2 cols/thread, 4 chunks of 32 outputs, 512 blocks x 128 thr.
// ---------------------------------------------------------------------------
__global__ __launch_bounds__(128) void k_y(
    const float* __restrict__ x, const float* __restrict__ m,
    const float* __restrict__ u, const float* __restrict__ h)
{
    __shared__ unsigned long long WPs[68][64];   // weight pairs
    __shared__ unsigned long long bep[64];       // bias pairs
    for (int i = threadIdx.x; i < 68 * 64; i += 128) {
        int cp = i >> 6, p = i & 63;
        WPs[cp][p] = pack2(g_weff[(2 * p) * 68 + cp], g_weff[(2 * p + 1) * 68 + cp]);
    }
    if (threadIdx.x < 64)
        bep[threadIdx.x] = pack2(g_beff[2 * threadIdx.x], g_beff[2 * threadIdx.x + 1]);
    __syncthreads();

    int b = blockIdx.x >> 2;
    int n0 = (blockIdx.x & 3) * 256 + threadIdx.x * 2;

    for (int ch = 0; ch < 4; ch++) {
        int p0 = ch * 16;                        // 16 pairs = 32 outputs
        unsigned long long acc[16][2];
#pragma unroll
        for (int i = 0; i < 16; i++) {
            unsigned long long bv = bep[p0 + i];
            acc[i][0] = bv; acc[i][1] = bv;
        }

#define YACC(cp, ptr) do {                                                     \
        float2 _v = *(const float2*)(ptr);                                     \
        unsigned long long _v0 = bcast2(_v.x), _v1 = bcast2(_v.y);             \
        _Pragma("unroll")                                                      \
        for (int i = 0; i < 16; i++) {                                         \
            unsigned long long _wp = WPs[cp][p0 + i];                          \
            ffma2(acc[i][0], _wp, _v0);                                        \
            ffma2(acc[i][1], _wp, _v1);                                        \
        }                                                                      \
    } while (0)

        YACC(0, &x[b * 1024 + n0]);
        YACC(1, &m[b * 1024 + n0]);
        YACC(2, &u[b * 2048 + n0]);
        YACC(3, &u[b * 2048 + 1024 + n0]);
        for (int c = 0; c < 64; c++)
            YACC(4 + c, &h[(b * 64 + c) * 1024 + n0]);
#undef YACC

#pragma unroll
        for (int i = 0; i < 16; i++) {
            float2 c0 = unpack2(acc[i][0]);   // (o=2i, n0), (o=2i+1, n0)
            float2 c1 = unpack2(acc[i][1]);   // (o=2i, n0+1), (o=2i+1, n0+1)
#pragma unroll
            for (int q = 0; q < 2; q++) {
                int op = ch * 32 + 2 * i + q;
                float v0 = q ? c0.y : c0.x;
                float v1 = q ? c1.y : c1.x;
                int s = op >> 6, oc = op & 63;
                size_t yi = (size_t)(b * 64 + oc) * K2 + s * 1024 + n0;
                __nv_bfloat162 hp = __halves2bfloat162(
                    __float2bfloat16(v0), __float2bfloat16(v1));
                *(unsigned*)&g_yhi[yi] = *(unsigned*)&hp;
            }
        }
    }
}

// ---------------------------------------------------------------------------
// GEMM: single-pass bf16 mma.sync   gc = yhi @ ahi (+ bias)
// BM=128 BN=128 BK=64; 4 warps (2x2), warp tile 64x64 (halves ldsm traffic);
// XOR-swizzled smem, 3-stage cp.async, 128 thr/CTA, 2 CTAs/SM.
// ---------------------------------------------------------------------------
#define BM 128
#define BN 128
#define BK 64
#define ASTG (128 * 128)
#define STGB (2 * ASTG)
#define GDYN (3 * STGB)
#define NCHK 32

__device__ __forceinline__ void load_chunk(unsigned base, int st, int t,
                                           int bm, int bn, int tid)
{
    int k0 = t * BK;
    int s = k0 >> 10;
    int v0 = k0 & 1023;
    unsigned ab = base + st * STGB;
    unsigned bb = ab + ASTG;
#pragma unroll
    for (int i = 0; i < 8; i++) {               // A: 1024 16B units / 128 thr
        int u2 = tid + i * 128;
        int row = u2 >> 3, j = u2 & 7;
        CP16(ab + row * 128 + ((j ^ (row & 7)) * 16),
             (const char*)(g_yhi + (size_t)(bm + row) * K2 + k0 + j * 8));
    }
#pragma unroll
    for (int i = 0; i < 8; i++) {               // B: 1024 16B units
        int u2 = tid + i * 128;
        int row = u2 >> 3, j = u2 & 7;
        CP16(bb + row * 128 + ((j ^ (row & 7)) * 16),
             (const char*)(g_ahi + (size_t)s * 1048576 +
                           (size_t)(bn + row) * 1024 + v0 + j * 8));
    }
    CP_COMMIT();
}

__global__ __launch_bounds__(128, 2) void k_gemm_mma(const float* __restrict__ b_gc)
{
    extern __shared__ __align__(16) char dsm[];
    unsigned base = s2u(dsm);

    int tid = threadIdx.x;
    int lane = tid & 31;
    int wid = tid >> 5;
    int wm = wid >> 1;        // 0..1 (64-row group)
    int wn = wid & 1;         // 0..1 (64-col group)
    int bm = blockIdx.y * BM;
    int bn = blockIdx.x * BN;

    float acc[4][8][4];
#pragma unroll
    for (int i = 0; i < 4; i++)
#pragma unroll
        for (int j = 0; j < 8; j++)
#pragma unroll
            for (int q = 0; q < 4; q++) acc[i][j][q] = 0.f;

    load_chunk(base, 0, 0, bm, bn, tid);
    load_chunk(base, 1, 1, bm, bn, tid);

    int st = 0;
    for (int t = 0; t < NCHK; t++) {
        if (t == NCHK - 1) asm volatile("cp.async.wait_group 0;" ::: "memory");
        else               asm volatile("cp.async.wait_group 1;" ::: "memory");
        __syncthreads();

        if (t + 2 < NCHK) {
            int st2 = st + 2; if (st2 >= 3) st2 -= 3;
            load_chunk(base, st2, t + 2, bm, bn, tid);
        }

        unsigned abuf = base + st * STGB;
        unsigned bbuf = abuf + ASTG;

#pragma unroll
        for (int kk = 0; kk < 4; kk++) {
            unsigned ar[4][4];
#pragma unroll
            for (int mf = 0; mf < 4; mf++) {
                int mrow = wm * 64 + mf * 16 + (lane & 7) + ((lane >> 3) & 1) * 8;
                int uidx = kk * 2 + (lane >> 4);
                ldsm4(ar[mf], abuf + mrow * 128 + ((uidx ^ (mrow & 7)) * 16));
            }
            unsigned br[4][4];
#pragma unroll
            for (int nt = 0; nt < 4; nt++) {
                int nrow = wn * 64 + nt * 16 + (lane & 7) + (lane >> 4) * 8;
                int uidx = kk * 2 + ((lane >> 3) & 1);
                ldsm4(br[nt], bbuf + nrow * 128 + ((uidx ^ (nrow & 7)) * 16));
            }
#pragma unroll
            for (int mf = 0; mf < 4; mf++)
#pragma unroll
                for (int nt = 0; nt < 4; nt++) {
                    mma16816(acc[mf][nt * 2 + 0], ar[mf], br[nt][0], br[nt][1]);
                    mma16816(acc[mf][nt * 2 + 1], ar[mf], br[nt][2], br[nt][3]);
                }
        }
        st++; if (st >= 3) st = 0;
    }

#pragma unroll
    for (int mf = 0; mf < 4; mf++) {
        int r0 = bm + wm * 64 + mf * 16 + (lane >> 2);
        float bv0 = __ldg(&b_gc[r0 & 63]);
        float bv1 = __ldg(&b_gc[(r0 + 8) & 63]);
#pragma unroll
        for (int nf = 0; nf < 8; nf++) {
            int col = bn + wn * 64 + nf * 8 + (lane & 3) * 2;
            float* c4 = acc[mf][nf];
            *(float2*)&g_gc[(size_t)r0 * 1024 + col] =
                make_float2(c4[0] + bv0, c4[1] + bv0);
            *(float2*)&g_gc[(size_t)(r0 + 8) * 1024 + col] =
                make_float2(c4[2] + bv1, c4[3] + bv1);
        }
    }
}

// ---------------------------------------------------------------------------
// k_out_mma (unchanged from R10 — proven).
// ---------------------------------------------------------------------------
#define ODYN 98304

__global__ __launch_bounds__(256, 2) void k_out_mma(
    const float* __restrict__ h, const float* __restrict__ W_out,
    const float* __restrict__ b_out, const float* __restrict__ W_read,
    const float* __restrict__ b_read, const float* __restrict__ prelu_w,
    float* __restrict__ out)
{
    extern __shared__ __align__(16) char dsm[];
    unsigned As = s2u(dsm);
    unsigned Bs = As + 32768;
    float* prelu_s = (float*)dsm;               // reused after mma (132 stride)

    __shared__ float Wr_s[128];
    __shared__ float bo_s[64];

    int tid = threadIdx.x;
    int lane = tid & 31;
    int wid = tid >> 5;
    int b = blockIdx.x >> 3;
    int n0 = (blockIdx.x & 7) * 128;

    if (tid < 128) Wr_s[tid] = W_read[tid];
    if (tid >= 128 && tid < 192) bo_s[tid - 128] = b_out[tid - 128];

    // ---- stage B: gc (k 0..63) ----
#pragma unroll
    for (int i = 0; i < 8; i++) {
        int u = tid + i * 256;
        int c = u >> 5, f4 = u & 31;
        float4 g = *(const float4*)&g_gc[(size_t)(b * 64 + c) * 1024 + n0 + f4 * 4];
        float vv[4] = {g.x, g.y, g.z, g.w};
#pragma unroll
        for (int j = 0; j < 4; j++) {
            int n = f4 * 4 + j;
            STS16(Bs + n * 512 + (((c >> 3) ^ (n & 7)) * 16) + (c & 7) * 2,
                  bf16u(vv[j]));
        }
    }
    // ---- stage B: h hi (k 64.. & 192..), lo (k 128..) ----
#pragma unroll
    for (int i = 0; i < 8; i++) {
        int u = tid + i * 256;
        int c = u >> 5, f4 = u & 31;
        float4 hv = *(const float4*)&h[(size_t)(b * 64 + c) * 1024 + n0 + f4 * 4];
        float vv[4] = {hv.x, hv.y, hv.z, hv.w};
#pragma unroll
        for (int j = 0; j < 4; j++) {
            int n = f4 * 4 + j;
            __nv_bfloat16 hb = __float2bfloat16(vv[j]);
            unsigned short hu = *(unsigned short*)&hb;
            unsigned short lu = bf16u(vv[j] - __bfloat162float(hb));
            unsigned rowb = Bs + n * 512;
            unsigned x7 = (n & 7);
            STS16(rowb + (((8  + (c >> 3)) ^ x7) * 16) + (c & 7) * 2, hu);
            STS16(rowb + (((24 + (c >> 3)) ^ x7) * 16) + (c & 7) * 2, hu);
            STS16(rowb + (((16 + (c >> 3)) ^ x7) * 16) + (c & 7) * 2, lu);
        }
    }
    // ---- stage A: W_out [64 o x 128 c] ----
#pragma unroll
    for (int i = 0; i < 8; i++) {
        int u = tid + i * 256;
        int o = u >> 5, f4 = u & 31;
        float4 w = *(const float4*)&W_out[o * 128 + f4 * 4];
        float vv[4] = {w.x, w.y, w.z, w.w};
        unsigned rowa = As + o * 512;
        unsigned x7 = (o & 7);
#pragma unroll
        for (int j = 0; j < 4; j++) {
            int c = f4 * 4 + j;
            if (c < 64) {
                STS16(rowa + (((c >> 3) ^ x7) * 16) + (c & 7) * 2, bf16u(vv[j]));
            } else {
                __nv_bfloat16 hb = __float2bfloat16(vv[j]);
                unsigned short hu = *(unsigned short*)&hb;
                unsigned short lu = bf16u(vv[j] - __bfloat162float(hb));
                int k1 = c;          // 64..127  (hi)
                int k2 = c + 64;     // 128..191 (hi)
                int k3 = c + 128;    // 192..255 (lo)
                STS16(rowa + (((k1 >> 3) ^ x7) * 16) + (k1 & 7) * 2, hu);
                STS16(rowa + (((k2 >> 3) ^ x7) * 16) + (k2 & 7) * 2, hu);
                STS16(rowa + (((k3 >> 3) ^ x7) * 16) + (k3 & 7) * 2, lu);
            }
        }
    }
    __syncthreads();

    // ---- mma: M=64 N=128 K=256; 8 warps, warp tile m16 x n64 ----
    int wm = wid >> 1;   // 0..3
    int wn = wid & 1;    // 0..1
    float acc[8][4];
#pragma unroll
    for (int j = 0; j < 8; j++)
#pragma unroll
        for (int q = 0; q < 4; q++) acc[j][q] = 0.f;

#pragma unroll
    for (int kk = 0; kk < 16; kk++) {
        unsigned ar[4];
        int mrow = wm * 16 + (lane & 7) + ((lane >> 3) & 1) * 8;
        int uA = kk * 2 + (lane >> 4);
        ldsm4(ar, As + mrow * 512 + ((uA ^ (mrow & 7)) * 16));
        unsigned br[4][4];
#pragma unroll
        for (int nt = 0; nt < 4; nt++) {
            int nrow = wn * 64 + nt * 16 + (lane & 7) + (lane >> 4) * 8;
            int uB = kk * 2 + ((lane >> 3) & 1);
            ldsm4(br[nt], Bs + nrow * 512 + ((uB ^ (nrow & 7)) * 16));
        }
#pragma unroll
        for (int nt = 0; nt < 4; nt++) {
            mma16816(acc[nt * 2 + 0], ar, br[nt][0], br[nt][1]);
            mma16816(acc[nt * 2 + 1], ar, br[nt][2], br[nt][3]);
        }
    }
    __syncthreads();   // smem reads done; safe to overwrite with prelu_s

    // ---- epilogue: bias + PReLU -> out2 + prelu_s ----
    float pw = __ldg(prelu_w);
    float* out2 = out + (size_t)Bb * Nn;
    int o0 = wm * 16 + (lane >> 2);
    float b0v = bo_s[o0];
    float b1v = bo_s[o0 + 8];
#pragma unroll
    for (int nt = 0; nt < 4; nt++)
#pragma unroll
        for (int q = 0; q < 2; q++) {
            int ncol = wn * 64 + nt * 16 + q * 8 + (lane & 3) * 2;
            float* c4 = acc[nt * 2 + q];
            float v0 = c4[0] + b0v, v1 = c4[1] + b0v;
            float v2 = c4[2] + b1v, v3 = c4[3] + b1v;
            float p0 = v0 >= 0.f ? v0 : pw * v0;
            float p1 = v1 >= 0.f ? v1 : pw * v1;
            float p2 = v2 >= 0.f ? v2 : pw * v2;
            float p3 = v3 >= 0.f ? v3 : pw * v3;
            *(float2*)&out2[(size_t)(b * 128 + o0) * 1024 + n0 + ncol] =
                make_float2(p0, p1);
            *(float2*)&out2[(size_t)(b * 128 + o0 + 8) * 1024 + n0 + ncol] =
                make_float2(p2, p3);
            *(float2*)&prelu_s[o0 * 132 + ncol] = make_float2(p0, p1);
            *(float2*)&prelu_s[(o0 + 8) * 132 + ncol] = make_float2(p2, p3);
        }
    __syncthreads();

    // ---- readout conv (tid<128) + exact h copy (tid>=128) ----
    if (tid < 128) {
        int n = tid;
        float racc = __ldg(b_read);
        for (int o = 0; o < 64; o++)
            racc = fmaf(Wr_s[o], prelu_s[o * 132 + n], racc);
        for (int c = 0; c < 64; c++)
            racc = fmaf(Wr_s[64 + c],
                        h[(size_t)(b * 64 + c) * 1024 + n0 + n], racc);
        out[(size_t)b * 1024 + n0 + n] = racc;
    } else {
        int t2 = tid - 128;
#pragma unroll
        for (int i = 0; i < 16; i++) {
            int u = t2 + i * 128;
            int c = u >> 5, f4 = u & 31;
            float4 hv = *(const float4*)&h[(size_t)(b * 64 + c) * 1024 + n0 + f4 * 4];
            *(float4*)&out2[(size_t)(b * 128 + 64 + c) * 1024 + n0 + f4 * 4] = hv;
        }
    }
}

// ---------------------------------------------------------------------------
extern "C" void kernel_launch(void* const* d_in, const int* in_sizes, int n_in,
                              void* d_out, int out_size)
{
    const float* x      = (const float*)d_in[0];
    const float* m      = (const float*)d_in[1];
    const float* u      = (const float*)d_in[2];
    const float* h      = (const float*)d_in[3];
    const float* adj    = (const float*)d_in[4];
    const float* W_in   = (const float*)d_in[5];
    const float* b_in   = (const float*)d_in[6];
    const float* W_gc   = (const float*)d_in[7];
    const float* b_gc   = (const float*)d_in[8];
    const float* W_out  = (const float*)d_in[9];
    const float* b_out  = (const float*)d_in[10];
    const float* W_read = (const float*)d_in[11];
    const float* b_read = (const float*)d_in[12];
    const float* prelu  = (const float*)d_in[13];
    float* out = (float*)d_out;

    cudaFuncSetAttribute(k_gemm_mma, cudaFuncAttributeMaxDynamicSharedMemorySize, GDYN);
    cudaFuncSetAttribute(k_out_mma, cudaFuncAttributeMaxDynamicSharedMemorySize, ODYN);

    k_adj<<<2048, 256>>>(adj);
    k_weff<<<35, 256>>>(W_in, b_in, W_gc);
    k_y<<<512, 128>>>(x, m, u, h);
    dim3 g(Nn / BN, (Bb * DMdim) / BM);   // (8, 64) = 512 CTAs
    k_gemm_mma<<<g, 128, GDYN>>>(b_gc);
    k_out_mma<<<1024, 256, ODYN>>>(h, W_out, b_out, W_read, b_read, prelu, out);
}

// round 12
// speedup vs baseline: 3.5337x; 1.2268x over previous
#include <cuda_runtime.h>
#include <cuda_bf16.h>

#define Bb 128
#define Nn 1024
#define DMdim 64
#define K2 2048   // S * Nn

// Scratch (no allocs): static device globals
__device__ __nv_bfloat16 g_yhi[(size_t)8192 * 2048];     // 32 MB
__device__ __nv_bfloat16 g_ahi[2 * 1024 * 1024];         // 4 MB
__device__ unsigned char g_gcT[(size_t)1024 * 16384];    // 16 MB: 1024 tiles [o64][n128] bf16 swizzled
__device__ float g_weff[128 * 68];
__device__ float g_beff[128];

// ---------------------------------------------------------------------------
__device__ __forceinline__ unsigned s2u(const void* p) {
    unsigned a;
    asm("{ .reg .u64 t; cvta.to.shared.u64 t, %1; cvt.u32.u64 %0, t; }"
        : "=r"(a) : "l"(p));
    return a;
}
#define CP16(dst, src) \
    asm volatile("cp.async.cg.shared.global [%0], [%1], 16;" :: "r"(dst), "l"(src))
#define CP_COMMIT() asm volatile("cp.async.commit_group;" ::: "memory")
#define STS16(addr, v) \
    asm volatile("st.shared.u16 [%0], %1;" :: "r"(addr), "h"(v))
#define STS64(addr, v) \
    asm volatile("st.shared.b64 [%0], %1;" :: "r"(addr), "l"(v))

__device__ __forceinline__ unsigned short bf16u(float f) {
    __nv_bfloat16 t = __float2bfloat16(f);
    return *(unsigned short*)&t;
}
__device__ __forceinline__ unsigned long long packu2(unsigned a, unsigned b) {
    unsigned long long r;
    asm("mov.b64 %0, {%1, %2};" : "=l"(r) : "r"(a), "r"(b));
    return r;
}

// packed f32x2 helpers (FFMA2 path)
__device__ __forceinline__ unsigned long long pack2(float a, float b) {
    unsigned long long r;
    asm("mov.b64 %0, {%1, %2};" : "=l"(r) : "f"(a), "f"(b));
    return r;
}
__device__ __forceinline__ unsigned long long bcast2(float a) {
    unsigned long long r;
    asm("mov.b64 %0, {%1, %1};" : "=l"(r) : "f"(a));
    return r;
}
__device__ __forceinline__ void ffma2(unsigned long long& d,
                                      unsigned long long a, unsigned long long b) {
    asm("fma.rn.f32x2 %0, %1, %2, %0;" : "+l"(d) : "l"(a), "l"(b));
}
__device__ __forceinline__ float2 unpack2(unsigned long long v) {
    float x, y;
    asm("mov.b64 {%0, %1}, %2;" : "=f"(x), "=f"(y) : "l"(v));
    return make_float2(x, y);
}

__device__ __forceinline__ void ldsm4(unsigned* r, unsigned addr) {
    asm volatile("ldmatrix.sync.aligned.m8n8.x4.shared.b16 {%0,%1,%2,%3}, [%4];"
                 : "=r"(r[0]), "=r"(r[1]), "=r"(r[2]), "=r"(r[3]) : "r"(addr));
}
__device__ __forceinline__ void ldsm4t(unsigned* r, unsigned addr) {
    asm volatile("ldmatrix.sync.aligned.m8n8.x4.trans.shared.b16 {%0,%1,%2,%3}, [%4];"
                 : "=r"(r[0]), "=r"(r[1]), "=r"(r[2]), "=r"(r[3]) : "r"(addr));
}
__device__ __forceinline__ void mma16816(float* c, const unsigned* a,
                                         unsigned b0, unsigned b1) {
    asm volatile(
        "mma.sync.aligned.m16n8k16.row.col.f32.bf16.bf16.f32 "
        "{%0,%1,%2,%3}, {%4,%5,%6,%7}, {%8,%9}, {%0,%1,%2,%3};"
        : "+f"(c[0]), "+f"(c[1]), "+f"(c[2]), "+f"(c[3])
        : "r"(a[0]), "r"(a[1]), "r"(a[2]), "r"(a[3]), "r"(b0), "r"(b1));
}

// ---------------------------------------------------------------------------
// adj -> bf16
// ---------------------------------------------------------------------------
__global__ __launch_bounds__(256) void k_adj(const float* __restrict__ adj)
{
    int i = blockIdx.x * 256 + threadIdx.x;
    float4 v = ((const float4*)adj)[i];
    ((__nv_bfloat162*)g_ahi)[i * 2 + 0] = __halves2bfloat162(
        __float2bfloat16(v.x), __float2bfloat16(v.y));
    ((__nv_bfloat162*)g_ahi)[i * 2 + 1] = __halves2bfloat162(
        __float2bfloat16(v.z), __float2bfloat16(v.w));
}

// ---------------------------------------------------------------------------
// fold W_in into W_gc (parallel)
// ---------------------------------------------------------------------------
__global__ __launch_bounds__(256) void k_weff(
    const float* __restrict__ W_in, const float* __restrict__ b_in,
    const float* __restrict__ W_gc)
{
    int i = blockIdx.x * 256 + threadIdx.x;
    if (blockIdx.x < 34) {
        int op = i / 68, cp = i - op * 68;
        const float* wg = W_gc + (op & 63) * 128 + (op >> 6) * 64;
        float s = 0.f;
#pragma unroll 8
        for (int c = 0; c < 64; c++) s = fmaf(wg[c], W_in[c * 68 + cp], s);
        g_weff[op * 68 + cp] = s;
    } else if (threadIdx.x < 128) {
        int op = threadIdx.x;
        const float* wg = W_gc + (op & 63) * 128 + (op >> 6) * 64;
        float s = 0.f;
#pragma unroll 8
        for (int c = 0; c < 64; c++) s = fmaf(wg[c], b_in[c], s);
        g_beff[op] = s;
    }
}

// ---------------------------------------------------------------------------
// k_y: FFMA2, 2 cols/thread, 4 chunks of 32 outputs, 512 blocks x 128 thr.
// ---------------------------------------------------------------------------
__global__ __launch_bounds__(128) void k_y(
    const float* __restrict__ x, const float* __restrict__ m,
    const float* __restrict__ u, const float* __restrict__ h)
{
    __shared__ unsigned long long WPs[68][64];
    __shared__ unsigned long long bep[64];
    for (int i = threadIdx.x; i < 68 * 64; i += 128) {
        int cp = i >> 6, p = i & 63;
        WPs[cp][p] = pack2(g_weff[(2 * p) * 68 + cp], g_weff[(2 * p + 1) * 68 + cp]);
    }
    if (threadIdx.x < 64)
        bep[threadIdx.x] = pack2(g_beff[2 * threadIdx.x], g_beff[2 * threadIdx.x + 1]);
    __syncthreads();

    int b = blockIdx.x >> 2;
    int n0 = (blockIdx.x & 3) * 256 + threadIdx.x * 2;

    for (int ch = 0; ch < 4; ch++) {
        int p0 = ch * 16;
        unsigned long long acc[16][2];
#pragma unroll
        for (int i = 0; i < 16; i++) {
            unsigned long long bv = bep[p0 + i];
            acc[i][0] = bv; acc[i][1] = bv;
        }

#define YACC(cp, ptr) do {                                                     \
        float2 _v = *(const float2*)(ptr);                                     \
        unsigned long long _v0 = bcast2(_v.x), _v1 = bcast2(_v.y);             \
        _Pragma("unroll")                                                      \
        for (int i = 0; i < 16; i++) {                                         \
            unsigned long long _wp = WPs[cp][p0 + i];                          \
            ffma2(acc[i][0], _wp, _v0);                                        \
            ffma2(acc[i][1], _wp, _v1);                                        \
        }                                                                      \
    } while (0)

        YACC(0, &x[b * 1024 + n0]);
        YACC(1, &m[b * 1024 + n0]);
        YACC(2, &u[b * 2048 + n0]);
        YACC(3, &u[b * 2048 + 1024 + n0]);
        for (int c = 0; c < 64; c++)
            YACC(4 + c, &h[(b * 64 + c) * 1024 + n0]);
#undef YACC

#pragma unroll
        for (int i = 0; i < 16; i++) {
            float2 c0 = unpack2(acc[i][0]);
            float2 c1 = unpack2(acc[i][1]);
#pragma unroll
            for (int q = 0; q < 2; q++) {
                int op = ch * 32 + 2 * i + q;
                float v0 = q ? c0.y : c0.x;
                float v1 = q ? c1.y : c1.x;
                int s = op >> 6, oc = op & 63;
                size_t yi = (size_t)(b * 64 + oc) * K2 + s * 1024 + n0;
                __nv_bfloat162 hp = __halves2bfloat162(
                    __float2bfloat16(v0), __float2bfloat16(v1));
                *(unsigned*)&g_yhi[yi] = *(unsigned*)&hp;
            }
        }
    }
}

// ---------------------------------------------------------------------------
// GEMM: single-pass bf16 mma.sync, epilogue emits gcT bf16 swizzled tiles.
// BM=128 BN=128 BK=64; 4 warps (2x2), warp tile 64x64; 3-stage cp.async.
// ---------------------------------------------------------------------------
#define BM 128
#define BN 128
#define BK 64
#define ASTG (128 * 128)
#define STGB (2 * ASTG)
#define GDYN (3 * STGB)
#define NCHK 32

__device__ __forceinline__ void load_chunk(unsigned base, int st, int t,
                                           int bm, int bn, int tid)
{
    int k0 = t * BK;
    int s = k0 >> 10;
    int v0 = k0 & 1023;
    unsigned ab = base + st * STGB;
    unsigned bb = ab + ASTG;
#pragma unroll
    for (int i = 0; i < 8; i++) {
        int u2 = tid + i * 128;
        int row = u2 >> 3, j = u2 & 7;
        CP16(ab + row * 128 + ((j ^ (row & 7)) * 16),
             (const char*)(g_yhi + (size_t)(bm + row) * K2 + k0 + j * 8));
    }
#pragma unroll
    for (int i = 0; i < 8; i++) {
        int u2 = tid + i * 128;
        int row = u2 >> 3, j = u2 & 7;
        CP16(bb + row * 128 + ((j ^ (row & 7)) * 16),
             (const char*)(g_ahi + (size_t)s * 1048576 +
                           (size_t)(bn + row) * 1024 + v0 + j * 8));
    }
    CP_COMMIT();
}

__global__ __launch_bounds__(128, 2) void k_gemm_mma(const float* __restrict__ b_gc)
{
    extern __shared__ __align__(16) char dsm[];
    unsigned base = s2u(dsm);

    int tid = threadIdx.x;
    int lane = tid & 31;
    int wid = tid >> 5;
    int wm = wid >> 1;
    int wn = wid & 1;
    int bm = blockIdx.y * BM;
    int bn = blockIdx.x * BN;

    float acc[4][8][4];
#pragma unroll
    for (int i = 0; i < 4; i++)
#pragma unroll
        for (int j = 0; j < 8; j++)
#pragma unroll
            for (int q = 0; q < 4; q++) acc[i][j][q] = 0.f;

    load_chunk(base, 0, 0, bm, bn, tid);
    load_chunk(base, 1, 1, bm, bn, tid);

    int st = 0;
    for (int t = 0; t < NCHK; t++) {
        if (t == NCHK - 1) asm volatile("cp.async.wait_group 0;" ::: "memory");
        else               asm volatile("cp.async.wait_group 1;" ::: "memory");
        __syncthreads();

        if (t + 2 < NCHK) {
            int st2 = st + 2; if (st2 >= 3) st2 -= 3;
            load_chunk(base, st2, t + 2, bm, bn, tid);
        }

        unsigned abuf = base + st * STGB;
        unsigned bbuf = abuf + ASTG;

#pragma unroll
        for (int kk = 0; kk < 4; kk++) {
            unsigned ar[4][4];
#pragma unroll
            for (int mf = 0; mf < 4; mf++) {
                int mrow = wm * 64 + mf * 16 + (lane & 7) + ((lane >> 3) & 1) * 8;
                int uidx = kk * 2 + (lane >> 4);
                ldsm4(ar[mf], abuf + mrow * 128 + ((uidx ^ (mrow & 7)) * 16));
            }
            unsigned br[4][4];
#pragma unroll
            for (int nt = 0; nt < 4; nt++) {
                int nrow = wn * 64 + nt * 16 + (lane & 7) + (lane >> 4) * 8;
                int uidx = kk * 2 + ((lane >> 3) & 1);
                ldsm4(br[nt], bbuf + nrow * 128 + ((uidx ^ (nrow & 7)) * 16));
            }
#pragma unroll
            for (int mf = 0; mf < 4; mf++)
#pragma unroll
                for (int nt = 0; nt < 4; nt++) {
                    mma16816(acc[mf][nt * 2 + 0], ar[mf], br[nt][0], br[nt][1]);
                    mma16816(acc[mf][nt * 2 + 1], ar[mf], br[nt][2], br[nt][3]);
                }
        }
        st++; if (st >= 3) st = 0;
    }

    // epilogue: bias + cvt bf16, store into gcT swizzled [o][n] tiles
#pragma unroll
    for (int mf = 0; mf < 4; mf++) {
        int r0 = bm + wm * 64 + mf * 16 + (lane >> 2);
#pragma unroll
        for (int nf = 0; nf < 8; nf++) {
            int col = bn + wn * 64 + nf * 8 + (lane & 3) * 2;
            int nt_ = col & 127;
            float* c4 = acc[mf][nf];
#pragma unroll
            for (int rr = 0; rr < 2; rr++) {
                int mrow = r0 + rr * 8;
                int bI = mrow >> 6, o = mrow & 63;
                float bias = __ldg(&b_gc[o]);
                __nv_bfloat162 pv = __halves2bfloat162(
                    __float2bfloat16(c4[rr * 2 + 0] + bias),
                    __float2bfloat16(c4[rr * 2 + 1] + bias));
                size_t off = (size_t)(bI * 8 + (col >> 7)) * 16384 +
                             o * 256 + (((nt_ >> 3) ^ (o & 7)) * 16) + (nt_ & 7) * 2;
                *(unsigned*)(g_gcT + off) = *(unsigned*)&pv;
            }
        }
    }
}

// ---------------------------------------------------------------------------
// k_out_mma v2: conflict-free staging.
//   A [o64][k192] rows 512B (non-trans ldsm):   Wgc 0-63 | Wh_hi 64-127 | Wh_lo 128-191
//   B gc: cp.async of precomputed gcT tile [o64][n128], trans ldsm
//   B h : staged [k128][n128] rows 256B (h_hi 0-63, h_lo 64-127), trans ldsm
//   mma kk 0..15: A-index akk = kk<8?kk:kk-4, B per table (h_hi reused).
// smem: A 32KB @0 | gc 16KB @32768 | h 32KB @49152. prelu_s reuses base.
// ---------------------------------------------------------------------------
#define ODYN 81920

__global__ __launch_bounds__(256, 2) void k_out_mma(
    const float* __restrict__ h, const float* __restrict__ W_out,
    const float* __restrict__ b_out, const float* __restrict__ W_read,
    const float* __restrict__ b_read, const float* __restrict__ prelu_w,
    float* __restrict__ out)
{
    extern __shared__ __align__(16) char dsm[];
    unsigned As = s2u(dsm);
    unsigned gcA = As + 32768;
    unsigned hA = As + 49152;
    float* prelu_s = (float*)dsm;

    __shared__ float Wr_s[128];
    __shared__ float bo_s[64];

    int tid = threadIdx.x;
    int lane = tid & 31;
    int wid = tid >> 5;
    int b = blockIdx.x >> 3;
    int n0 = (blockIdx.x & 7) * 128;

    // gc tile via cp.async (tile index == blockIdx.x)
    const char* gsrc = (const char*)g_gcT + (size_t)blockIdx.x * 16384;
#pragma unroll
    for (int i = 0; i < 4; i++) {
        int u = tid + i * 256;
        CP16(gcA + u * 16, gsrc + u * 16);
    }
    CP_COMMIT();

    if (tid < 128) Wr_s[tid] = W_read[tid];
    if (tid >= 128 && tid < 192) bo_s[tid - 128] = b_out[tid - 128];

    // ---- stage h: [c][n] rows 256B, hi rows 0-63, lo rows 64-127 ----
#pragma unroll
    for (int i = 0; i < 8; i++) {
        int u = tid + i * 256;
        int c = u >> 5, nf4 = u & 31, n = nf4 * 4;
        float4 hv = *(const float4*)&h[(size_t)(b * 64 + c) * 1024 + n0 + n];
        __nv_bfloat16 h0 = __float2bfloat16(hv.x);
        __nv_bfloat16 h1 = __float2bfloat16(hv.y);
        __nv_bfloat16 h2 = __float2bfloat16(hv.z);
        __nv_bfloat16 h3 = __float2bfloat16(hv.w);
        __nv_bfloat162 hp0 = __halves2bfloat162(h0, h1);
        __nv_bfloat162 hp1 = __halves2bfloat162(h2, h3);
        unsigned long long hip = packu2(*(unsigned*)&hp0, *(unsigned*)&hp1);
        __nv_bfloat162 lp0 = __halves2bfloat162(
            __float2bfloat16(hv.x - __bfloat162float(h0)),
            __float2bfloat16(hv.y - __bfloat162float(h1)));
        __nv_bfloat162 lp1 = __halves2bfloat162(
            __float2bfloat16(hv.z - __bfloat162float(h2)),
            __float2bfloat16(hv.w - __bfloat162float(h3)));
        unsigned long long lop = packu2(*(unsigned*)&lp0, *(unsigned*)&lp1);
        unsigned sw = (((n >> 3) ^ (c & 7)) * 16) + (n & 7) * 2;
        STS64(hA + c * 256 + sw, hip);
        STS64(hA + (c + 64) * 256 + sw, lop);
    }
    // ---- stage A: W_out [64 o][k192] rows 512B ----
#pragma unroll
    for (int i = 0; i < 8; i++) {
        int u = tid + i * 256;
        int o = u >> 5, f4 = u & 31;
        float4 w = *(const float4*)&W_out[o * 128 + f4 * 4];
        float vv[4] = {w.x, w.y, w.z, w.w};
        unsigned rowa = As + o * 512;
        unsigned x7 = (o & 7);
#pragma unroll
        for (int j = 0; j < 4; j++) {
            int c = f4 * 4 + j;
            if (c < 64) {
                STS16(rowa + (((c >> 3) ^ x7) * 16) + (c & 7) * 2, bf16u(vv[j]));
            } else {
                __nv_bfloat16 hb = __float2bfloat16(vv[j]);
                unsigned short hu = *(unsigned short*)&hb;
                unsigned short lu = bf16u(vv[j] - __bfloat162float(hb));
                int k1 = c;          // 64..127  Wh_hi
                int k2 = c + 64;     // 128..191 Wh_lo
                STS16(rowa + (((k1 >> 3) ^ x7) * 16) + (k1 & 7) * 2, hu);
                STS16(rowa + (((k2 >> 3) ^ x7) * 16) + (k2 & 7) * 2, lu);
            }
        }
    }
    asm volatile("cp.async.wait_group 0;" ::: "memory");
    __syncthreads();

    // ---- mma: M=64 N=128, 16 k16-steps; 8 warps, warp tile m16 x n64 ----
    int wm = wid >> 1;   // 0..3
    int wn = wid & 1;    // 0..1
    float acc[8][4];
#pragma unroll
    for (int j = 0; j < 8; j++)
#pragma unroll
        for (int q = 0; q < 4; q++) acc[j][q] = 0.f;

#pragma unroll
    for (int kk = 0; kk < 16; kk++) {
        int akk = (kk < 8) ? kk : kk - 4;
        unsigned ar[4];
        int mrow = wm * 16 + (lane & 7) + ((lane >> 3) & 1) * 8;
        int uA = akk * 2 + (lane >> 4);
        ldsm4(ar, As + mrow * 512 + ((uA ^ (mrow & 7)) * 16));

        unsigned barea; int kbase;
        if (kk < 4)       { barea = gcA; kbase = kk * 16; }
        else if (kk < 8)  { barea = hA;  kbase = (kk - 4) * 16; }
        else if (kk < 12) { barea = hA;  kbase = 64 + (kk - 8) * 16; }
        else              { barea = hA;  kbase = (kk - 12) * 16; }
        int kr = kbase + (lane & 7) + ((lane >> 3) & 1) * 8;

        unsigned br[4][4];
#pragma unroll
        for (int nt = 0; nt < 4; nt++) {
            int nu = ((wn * 64 + nt * 16) >> 3) + (lane >> 4);
            ldsm4t(br[nt], barea + kr * 256 + ((nu ^ (kr & 7)) * 16));
        }
#pragma unroll
        for (int nt = 0; nt < 4; nt++) {
            mma16816(acc[nt * 2 + 0], ar, br[nt][0], br[nt][1]);
            mma16816(acc[nt * 2 + 1], ar, br[nt][2], br[nt][3]);
        }
    }
    __syncthreads();   // smem reads done; safe to overwrite with prelu_s

    // ---- epilogue: bias + PReLU -> out2 + prelu_s ----
    float pw = __ldg(prelu_w);
    float* out2 = out + (size_t)Bb * Nn;
    int o0 = wm * 16 + (lane >> 2);
    float b0v = bo_s[o0];
    float b1v = bo_s[o0 + 8];
#pragma unroll
    for (int nt = 0; nt < 4; nt++)
#pragma unroll
        for (int q = 0; q < 2; q++) {
            int ncol = wn * 64 + nt * 16 + q * 8 + (lane & 3) * 2;
            float* c4 = acc[nt * 2 + q];
            float v0 = c4[0] + b0v, v1 = c4[1] + b0v;
            float v2 = c4[2] + b1v, v3 = c4[3] + b1v;
            float p0 = v0 >= 0.f ? v0 : pw * v0;
            float p1 = v1 >= 0.f ? v1 : pw * v1;
            float p2 = v2 >= 0.f ? v2 : pw * v2;
            float p3 = v3 >= 0.f ? v3 : pw * v3;
            *(float2*)&out2[(size_t)(b * 128 + o0) * 1024 + n0 + ncol] =
                make_float2(p0, p1);
            *(float2*)&out2[(size_t)(b * 128 + o0 + 8) * 1024 + n0 + ncol] =
                make_float2(p2, p3);
            *(float2*)&prelu_s[o0 * 132 + ncol] = make_float2(p0, p1);
            *(float2*)&prelu_s[(o0 + 8) * 132 + ncol] = make_float2(p2, p3);
        }
    __syncthreads();

    // ---- readout conv (tid<128) + exact h copy (tid>=128) ----
    if (tid < 128) {
        int n = tid;
        float racc = __ldg(b_read);
        for (int o = 0; o < 64; o++)
            racc = fmaf(Wr_s[o], prelu_s[o * 132 + n], racc);
        for (int c = 0; c < 64; c++)
            racc = fmaf(Wr_s[64 + c],
                        h[(size_t)(b * 64 + c) * 1024 + n0 + n], racc);
        out[(size_t)b * 1024 + n0 + n] = racc;
    } else {
        int t2 = tid - 128;
#pragma unroll
        for (int i = 0; i < 16; i++) {
            int u = t2 + i * 128;
            int c = u >> 5, f4 = u & 31;
            float4 hv = *(const float4*)&h[(size_t)(b * 64 + c) * 1024 + n0 + f4 * 4];
            *(float4*)&out2[(size_t)(b * 128 + 64 + c) * 1024 + n0 + f4 * 4] = hv;
        }
    }
}

// ---------------------------------------------------------------------------
extern "C" void kernel_launch(void* const* d_in, const int* in_sizes, int n_in,
                              void* d_out, int out_size)
{
    const float* x      = (const float*)d_in[0];
    const float* m      = (const float*)d_in[1];
    const float* u      = (const float*)d_in[2];
    const float* h      = (const float*)d_in[3];
    const float* adj    = (const float*)d_in[4];
    const float* W_in   = (const float*)d_in[5];
    const float* b_in   = (const float*)d_in[6];
    const float* W_gc   = (const float*)d_in[7];
    const float* b_gc   = (const float*)d_in[8];
    const float* W_out  = (const float*)d_in[9];
    const float* b_out  = (const float*)d_in[10];
    const float* W_read = (const float*)d_in[11];
    const float* b_read = (const float*)d_in[12];
    const float* prelu  = (const float*)d_in[13];
    float* out = (float*)d_out;

    cudaFuncSetAttribute(k_gemm_mma, cudaFuncAttributeMaxDynamicSharedMemorySize, GDYN);
    cudaFuncSetAttribute(k_out_mma, cudaFuncAttributeMaxDynamicSharedMemorySize, ODYN);

    k_adj<<<2048, 256>>>(adj);
    k_weff<<<35, 256>>>(W_in, b_in, W_gc);
    k_y<<<512, 128>>>(x, m, u, h);
    dim3 g(Nn / BN, (Bb * DMdim) / BM);   // (8, 64) = 512 CTAs
    k_gemm_mma<<<g, 128, GDYN>>>(b_gc);
    k_out_mma<<<1024, 256, ODYN>>>(h, W_out, b_out, W_read, b_read, prelu, out);
}